// round 6
// baseline (speedup 1.0000x reference)
#include <cuda_runtime.h>
#include <cstdint>

#define B_  8
#define L_  2048
#define DM  128
#define NH  4
#define DK  32

typedef unsigned long long ull;

// Scratch (allocation-free rule: __device__ globals)
__device__ float g_Q[B_*NH*L_*DK];
__device__ float g_K[B_*NH*L_*DK];
__device__ float g_V[B_*NH*L_*DK];
__device__ float g_head[B_*L_*DM];

__device__ __forceinline__ ull pack2(float lo, float hi) {
    ull r; asm("mov.b64 %0, {%1, %2};" : "=l"(r) : "f"(lo), "f"(hi)); return r;
}
__device__ __forceinline__ void unpack2(ull v, float &lo, float &hi) {
    asm("mov.b64 {%0, %1}, %2;" : "=f"(lo), "=f"(hi) : "l"(v));
}
// Packed f32x2 FMA — only reachable via PTX (ptxas never auto-fuses)
#define FFMA2(d,a,b) asm("fma.rn.f32x2 %0, %1, %2, %0;" : "+l"(d) : "l"(a), "l"(b))
#define FMUL2(d,a,b) asm("mul.rn.f32x2 %0, %1, %2;" : "=l"(d) : "l"(a), "l"(b))

// ---------------------------------------------------------------------------
// Kernel 1: QKV projection.
// grid (L/128, B, 12): z picks (matrix in {Q,K,V}) x (head).
// Each thread owns one sequence position l, computes 32 outputs for the chunk.
// ---------------------------------------------------------------------------
__global__ __launch_bounds__(128) void qkv_kernel(const float* __restrict__ x,
                                                  const float* __restrict__ Wq,
                                                  const float* __restrict__ Wk,
                                                  const float* __restrict__ Wv) {
    __shared__ __align__(16) float Ws[DM*DK];
    const int t = threadIdx.x;
    const int l = blockIdx.x*128 + t;
    const int b = blockIdx.y;
    const int c = blockIdx.z;
    const int matsel = c >> 2, h = c & 3;

    const float* Wbase = (matsel==0 ? Wq : (matsel==1 ? Wk : Wv)) + h*DM*DK;
    #pragma unroll
    for (int i = 0; i < 32; i++) Ws[t + i*128] = Wbase[t + i*128];
    __syncthreads();

    const ull* W2 = (const ull*)Ws;
    ull acc[16];
    #pragma unroll
    for (int jp = 0; jp < 16; jp++) acc[jp] = 0ull;

    const float* xcol = x + (size_t)b*DM*L_ + l;
    #pragma unroll 4
    for (int d = 0; d < DM; d++) {
        float xv = __ldg(xcol + (size_t)d*L_);   // coalesced across threads
        ull xp = pack2(xv, xv);
        const ull* wrow = W2 + d*16;             // smem broadcast
        #pragma unroll
        for (int jp = 0; jp < 16; jp++) FFMA2(acc[jp], xp, wrow[jp]);
    }

    const float sc = (matsel == 0) ? 0.17677669529663687f : 1.0f;  // 1/sqrt(32) folded into Q
    float* dst = (matsel==0 ? g_Q : (matsel==1 ? g_K : g_V)) + (((size_t)b*NH + h)*L_ + l)*DK;
    #pragma unroll
    for (int jp = 0; jp < 16; jp++) {
        float lo, hi; unpack2(acc[jp], lo, hi);
        ((float2*)dst)[jp] = make_float2(lo*sc, hi*sc);
    }
}

// ---------------------------------------------------------------------------
// Kernel 2: flash attention. grid (L/128, NH, B), 128 threads.
// One thread owns one query row entirely: thread-local online softmax,
// K/V tiles (32 rows) staged in smem, all reads are warp broadcasts.
// Mask semantics (matching reference exactly):
//   keys  with mask==1 -> score = -1e30 before softmax
//   query rows with mask==0 -> output zeroed (attn * mask[q])
// ---------------------------------------------------------------------------
__global__ __launch_bounds__(128) void attn_kernel(const float* __restrict__ mask) {
    __shared__ __align__(16) float Ks[32*DK];
    __shared__ __align__(16) float Vs[32*DK];
    __shared__ float msk[32];

    const int t = threadIdx.x;
    const int qrow = blockIdx.x*128 + t;
    const int h = blockIdx.y, b = blockIdx.z;
    const size_t bh = (size_t)b*NH + h;

    // q row -> 16 packed f32x2 registers (scale already folded in)
    ull qp[16];
    const float4* qsrc = (const float4*)(g_Q + (bh*L_ + qrow)*DK);
    #pragma unroll
    for (int i = 0; i < 8; i++) {
        float4 f = qsrc[i];
        qp[2*i]   = pack2(f.x, f.y);
        qp[2*i+1] = pack2(f.z, f.w);
    }

    ull O2[16];
    #pragma unroll
    for (int i = 0; i < 16; i++) O2[i] = 0ull;
    float mval = -1e30f, lsum = 0.f;
    const float qm = mask[(size_t)b*L_ + qrow];

    const float4* Kbase = (const float4*)(g_K + bh*L_*DK);
    const float4* Vbase = (const float4*)(g_V + bh*L_*DK);
    const ull* K2 = (const ull*)Ks;
    const ull* V2 = (const ull*)Vs;

    for (int kt = 0; kt < L_/32; kt++) {
        __syncthreads();
        // contiguous 4KB tile copies, fully coalesced
        ((float4*)Ks)[t]     = Kbase[kt*256 + t];
        ((float4*)Ks)[t+128] = Kbase[kt*256 + t + 128];
        ((float4*)Vs)[t]     = Vbase[kt*256 + t];
        ((float4*)Vs)[t+128] = Vbase[kt*256 + t + 128];
        if (t < 32) msk[t] = mask[(size_t)b*L_ + kt*32 + t];
        __syncthreads();

        // S = q . K^T  (keys with mask==1 -> -1e30, exactly matching reference)
        float s[32];
        #pragma unroll
        for (int kk = 0; kk < 32; kk++) {
            const ull* krow = K2 + kk*16;
            ull a0 = 0ull, a1 = 0ull;
            #pragma unroll
            for (int dp = 0; dp < 16; dp += 2) {
                FFMA2(a0, qp[dp],   krow[dp]);
                FFMA2(a1, qp[dp+1], krow[dp+1]);
            }
            float l0,h0,l1,h1; unpack2(a0,l0,h0); unpack2(a1,l1,h1);
            float sv = (l0 + h0) + (l1 + h1);
            s[kk] = (msk[kk] > 0.5f) ? -1e30f : sv;
        }

        // online softmax (thread-local)
        float tm = s[0];
        #pragma unroll
        for (int kk = 1; kk < 32; kk++) tm = fmaxf(tm, s[kk]);
        float mnew = fmaxf(mval, tm);
        float r = __expf(mval - mnew);
        mval = mnew;
        float psum = 0.f;
        #pragma unroll
        for (int kk = 0; kk < 32; kk++) {
            float p = __expf(s[kk] - mnew);
            s[kk] = p;
            psum += p;
        }
        lsum = lsum * r + psum;

        ull rr = pack2(r, r);
        #pragma unroll
        for (int dp = 0; dp < 16; dp++) { ull tmp; FMUL2(tmp, O2[dp], rr); O2[dp] = tmp; }

        // O += P . V
        #pragma unroll
        for (int kk = 0; kk < 32; kk++) {
            ull pp = pack2(s[kk], s[kk]);
            const ull* vrow = V2 + kk*16;
            #pragma unroll
            for (int dp = 0; dp < 16; dp++) FFMA2(O2[dp], pp, vrow[dp]);
        }
    }

    // attn *= mask[q]: rows with mask==0 are zeroed, rows with mask==1 survive
    const float inv = (qm > 0.5f) ? (1.0f / lsum) : 0.0f;
    ull iv = pack2(inv, inv);
    float* hdst = g_head + ((size_t)b*L_ + qrow)*DM + h*DK;
    #pragma unroll
    for (int dp = 0; dp < 16; dp++) {
        ull tmp; FMUL2(tmp, O2[dp], iv);
        float lo, hi; unpack2(tmp, lo, hi);
        ((float2*)hdst)[dp] = make_float2(lo, hi);
    }
}

// ---------------------------------------------------------------------------
// Kernel 3: out = (head @ Wo)^T. grid (L/32, B), 256 threads.
// Thread = (l = t&31, 16 d-columns). Transposed stores are coalesced in l.
// ---------------------------------------------------------------------------
__global__ __launch_bounds__(256) void outproj_kernel(const float* __restrict__ Wo,
                                                      float* __restrict__ out) {
    __shared__ float Hs[32*129];                 // stride 129 -> conflict-free
    __shared__ __align__(16) float Wos[32*128];
    const int t = threadIdx.x;
    const int l0 = blockIdx.x*32;
    const int b = blockIdx.y;

    const float* hsrc = g_head + ((size_t)b*L_ + l0)*DM;
    #pragma unroll
    for (int i = 0; i < 16; i++) {
        int idx = t + i*256;
        Hs[(idx >> 7)*129 + (idx & 127)] = hsrc[idx];
    }

    const int l = t & 31, dbase = (t >> 5) * 16;
    ull acc[8];
    #pragma unroll
    for (int i = 0; i < 8; i++) acc[i] = 0ull;
    const ull* W2 = (const ull*)Wos;

    for (int ccb = 0; ccb < 4; ccb++) {
        __syncthreads();
        #pragma unroll
        for (int i = 0; i < 16; i++) Wos[t + i*256] = Wo[ccb*32*128 + t + i*256];
        __syncthreads();
        #pragma unroll 8
        for (int j = 0; j < 32; j++) {
            float hv = Hs[l*129 + ccb*32 + j];
            ull hh = pack2(hv, hv);
            const ull* wrow = W2 + j*64 + (dbase >> 1);  // warp broadcast
            #pragma unroll
            for (int i = 0; i < 8; i++) FFMA2(acc[i], hh, wrow[i]);
        }
    }

    #pragma unroll
    for (int i = 0; i < 8; i++) {
        float lo, hi; unpack2(acc[i], lo, hi);
        int d0 = dbase + 2*i;
        out[((size_t)b*DM + d0    )*L_ + l0 + l] = lo;   // coalesced in l
        out[((size_t)b*DM + d0 + 1)*L_ + l0 + l] = hi;
    }
}

extern "C" void kernel_launch(void* const* d_in, const int* in_sizes, int n_in,
                              void* d_out, int out_size) {
    const float* x    = (const float*)d_in[0];
    const float* mask = (const float*)d_in[1];
    const float* Wq   = (const float*)d_in[2];
    const float* Wk   = (const float*)d_in[3];
    const float* Wv   = (const float*)d_in[4];
    const float* Wo   = (const float*)d_in[5];
    float* out = (float*)d_out;

    qkv_kernel<<<dim3(L_/128, B_, 12), 128>>>(x, Wq, Wk, Wv);
    attn_kernel<<<dim3(L_/128, NH, B_), 128>>>(mask);
    outproj_kernel<<<dim3(L_/32, B_), 256>>>(Wo, out);
}

// round 8
// speedup vs baseline: 2.6884x; 2.6884x over previous
#include <cuda_runtime.h>
#include <cstdint>

#define B_  8
#define L_  2048
#define DM  128
#define NH  4
#define DK  32

typedef unsigned long long ull;

// Scratch (allocation-free rule: __device__ globals)
__device__ float g_Q[B_*NH*L_*DK];   // tf32-rounded
__device__ float g_K[B_*NH*L_*DK];   // tf32-rounded
__device__ float g_V[B_*NH*L_*DK];   // tf32-rounded
__device__ float g_head[B_*L_*DM];

__device__ __forceinline__ ull pack2(float lo, float hi) {
    ull r; asm("mov.b64 %0, {%1, %2};" : "=l"(r) : "f"(lo), "f"(hi)); return r;
}
__device__ __forceinline__ void unpack2(ull v, float &lo, float &hi) {
    asm("mov.b64 {%0, %1}, %2;" : "=f"(lo), "=f"(hi) : "l"(v));
}
#define FFMA2(d,a,b) asm("fma.rn.f32x2 %0, %1, %2, %0;" : "+l"(d) : "l"(a), "l"(b))
#define FMUL2(d,a,b) asm("mul.rn.f32x2 %0, %1, %2;" : "=l"(d) : "l"(a), "l"(b))

__device__ __forceinline__ unsigned cvt_tf32(float f) {
    unsigned u; asm("cvt.rna.tf32.f32 %0, %1;" : "=r"(u) : "f"(f)); return u;
}

// D += A(m16k8,tf32) * B(k8n8,tf32), fp32 accumulate
__device__ __forceinline__ void mma_tf32(float& c0, float& c1, float& c2, float& c3,
                                         unsigned a0, unsigned a1, unsigned a2, unsigned a3,
                                         unsigned b0, unsigned b1) {
    asm("mma.sync.aligned.m16n8k8.row.col.f32.tf32.tf32.f32 "
        "{%0,%1,%2,%3}, {%4,%5,%6,%7}, {%8,%9}, {%0,%1,%2,%3};"
        : "+f"(c0), "+f"(c1), "+f"(c2), "+f"(c3)
        : "r"(a0), "r"(a1), "r"(a2), "r"(a3), "r"(b0), "r"(b1));
}

// ---------------------------------------------------------------------------
// Kernel 1: QKV projection (unchanged math; outputs rounded to tf32 so the
// attention mainloop needs no per-fragment conversion).
// ---------------------------------------------------------------------------
__global__ __launch_bounds__(128) void qkv_kernel(const float* __restrict__ x,
                                                  const float* __restrict__ Wq,
                                                  const float* __restrict__ Wk,
                                                  const float* __restrict__ Wv) {
    __shared__ __align__(16) float Ws[DM*DK];
    const int t = threadIdx.x;
    const int l = blockIdx.x*128 + t;
    const int b = blockIdx.y;
    const int c = blockIdx.z;
    const int matsel = c >> 2, h = c & 3;

    const float* Wbase = (matsel==0 ? Wq : (matsel==1 ? Wk : Wv)) + h*DM*DK;
    #pragma unroll
    for (int i = 0; i < 32; i++) Ws[t + i*128] = Wbase[t + i*128];
    __syncthreads();

    const ull* W2 = (const ull*)Ws;
    ull acc[16];
    #pragma unroll
    for (int jp = 0; jp < 16; jp++) acc[jp] = 0ull;

    const float* xcol = x + (size_t)b*DM*L_ + l;
    #pragma unroll 4
    for (int d = 0; d < DM; d++) {
        float xv = __ldg(xcol + (size_t)d*L_);
        ull xp = pack2(xv, xv);
        const ull* wrow = W2 + d*16;
        #pragma unroll
        for (int jp = 0; jp < 16; jp++) FFMA2(acc[jp], xp, wrow[jp]);
    }

    const float sc = (matsel == 0) ? 0.17677669529663687f : 1.0f;  // 1/sqrt(32) into Q
    float* dst = (matsel==0 ? g_Q : (matsel==1 ? g_K : g_V)) + (((size_t)b*NH + h)*L_ + l)*DK;
    #pragma unroll
    for (int jp = 0; jp < 16; jp++) {
        float lo, hi; unpack2(acc[jp], lo, hi);
        dst[2*jp]   = __uint_as_float(cvt_tf32(lo*sc));
        dst[2*jp+1] = __uint_as_float(cvt_tf32(hi*sc));
    }
}

// ---------------------------------------------------------------------------
// Kernel 2: flash attention on mma.sync tf32.
// grid (L/64, NH, B), 128 threads = 4 warps; warp owns 16 q-rows (m16).
// K tiles of 32 keys; S = Q.K^T via 16 HMMA, online softmax in C-fragment
// layout (rows g, g+8 per thread; 4-lane shfl.bfly reductions), P->A-frag via
// shfl, O += P.V via 16 HMMA.
// Mask: keys mask==1 -> -1e30 pre-softmax; query rows mask==0 -> zeroed.
// smem strides 36/40 floats -> all fragment LDS conflict-free.
// ---------------------------------------------------------------------------
__global__ __launch_bounds__(128) void attn_kernel(const float* __restrict__ mask) {
    __shared__ __align__(16) float Ks[32*36];
    __shared__ __align__(16) float Vs[32*40];
    __shared__ float msk[32];

    const int t = threadIdx.x;
    const int lane = t & 31, w = t >> 5;
    const int g = lane >> 2, tg = lane & 3;
    const int h = blockIdx.y, b = blockIdx.z;
    const size_t bh = (size_t)b*NH + h;
    const int q0 = blockIdx.x*64 + w*16;

    // Q fragments (already tf32-rounded in memory): aQ[kc][4]
    unsigned aQ[4][4];
    const float* Qb = g_Q + (bh*L_ + q0)*DK;
    #pragma unroll
    for (int kc = 0; kc < 4; kc++) {
        int d0 = kc*8 + tg;
        aQ[kc][0] = __float_as_uint(Qb[(size_t)g*DK + d0]);
        aQ[kc][1] = __float_as_uint(Qb[(size_t)(g+8)*DK + d0]);
        aQ[kc][2] = __float_as_uint(Qb[(size_t)g*DK + d0 + 4]);
        aQ[kc][3] = __float_as_uint(Qb[(size_t)(g+8)*DK + d0 + 4]);
    }

    float o[4][4];
    #pragma unroll
    for (int i = 0; i < 4; i++)
        #pragma unroll
        for (int j = 0; j < 4; j++) o[i][j] = 0.f;
    float m0 = -1e30f, m1 = -1e30f, l0 = 0.f, l1 = 0.f;

    const float4* Kbase = (const float4*)(g_K + bh*L_*DK);
    const float4* Vbase = (const float4*)(g_V + bh*L_*DK);
    const int r0 = t >> 3, s0 = t & 7;

    for (int kt = 0; kt < L_/32; kt++) {
        __syncthreads();
        // stage K/V tile (32 keys x 32 d) with padded strides
        float4 kv0 = Kbase[kt*256 + t];
        float4 kv1 = Kbase[kt*256 + t + 128];
        float4 vv0 = Vbase[kt*256 + t];
        float4 vv1 = Vbase[kt*256 + t + 128];
        *(float4*)(Ks + r0*36 + s0*4)        = kv0;
        *(float4*)(Ks + (r0+16)*36 + s0*4)   = kv1;
        *(float4*)(Vs + r0*40 + s0*4)        = vv0;
        *(float4*)(Vs + (r0+16)*40 + s0*4)   = vv1;
        if (t < 32) msk[t] = mask[(size_t)b*L_ + kt*32 + t];
        __syncthreads();

        // ---- S = Q.K^T : 4 n-chunks x 4 k-chunks of m16n8k8
        float sc[4][4];
        #pragma unroll
        for (int nf = 0; nf < 4; nf++) {
            float c0 = 0.f, c1 = 0.f, c2 = 0.f, c3 = 0.f;
            #pragma unroll
            for (int kc = 0; kc < 4; kc++) {
                const float* kr = Ks + (nf*8 + g)*36 + kc*8 + tg;
                unsigned b0 = __float_as_uint(kr[0]);
                unsigned b1 = __float_as_uint(kr[4]);
                mma_tf32(c0, c1, c2, c3, aQ[kc][0], aQ[kc][1], aQ[kc][2], aQ[kc][3], b0, b1);
            }
            sc[nf][0] = c0; sc[nf][1] = c1; sc[nf][2] = c2; sc[nf][3] = c3;
        }

        // ---- key mask
        const int k2 = 2*tg;
        #pragma unroll
        for (int nf = 0; nf < 4; nf++) {
            float mk0 = msk[nf*8 + k2], mk1 = msk[nf*8 + k2 + 1];
            if (mk0 > 0.5f) { sc[nf][0] = -1e30f; sc[nf][2] = -1e30f; }
            if (mk1 > 0.5f) { sc[nf][1] = -1e30f; sc[nf][3] = -1e30f; }
        }

        // ---- online softmax (rows g and g+8)
        float tm0 = fmaxf(fmaxf(sc[0][0], sc[0][1]), fmaxf(sc[1][0], sc[1][1]));
        tm0 = fmaxf(tm0, fmaxf(fmaxf(sc[2][0], sc[2][1]), fmaxf(sc[3][0], sc[3][1])));
        float tm1 = fmaxf(fmaxf(sc[0][2], sc[0][3]), fmaxf(sc[1][2], sc[1][3]));
        tm1 = fmaxf(tm1, fmaxf(fmaxf(sc[2][2], sc[2][3]), fmaxf(sc[3][2], sc[3][3])));
        tm0 = fmaxf(tm0, __shfl_xor_sync(0xffffffffu, tm0, 1));
        tm0 = fmaxf(tm0, __shfl_xor_sync(0xffffffffu, tm0, 2));
        tm1 = fmaxf(tm1, __shfl_xor_sync(0xffffffffu, tm1, 1));
        tm1 = fmaxf(tm1, __shfl_xor_sync(0xffffffffu, tm1, 2));

        float mn0 = fmaxf(m0, tm0), mn1 = fmaxf(m1, tm1);
        float rs0 = __expf(m0 - mn0), rs1 = __expf(m1 - mn1);
        m0 = mn0; m1 = mn1;

        float ps0 = 0.f, ps1 = 0.f;
        #pragma unroll
        for (int nf = 0; nf < 4; nf++) {
            sc[nf][0] = __expf(sc[nf][0] - mn0);
            sc[nf][1] = __expf(sc[nf][1] - mn0);
            sc[nf][2] = __expf(sc[nf][2] - mn1);
            sc[nf][3] = __expf(sc[nf][3] - mn1);
            ps0 += sc[nf][0] + sc[nf][1];
            ps1 += sc[nf][2] + sc[nf][3];
        }
        ps0 += __shfl_xor_sync(0xffffffffu, ps0, 1);
        ps0 += __shfl_xor_sync(0xffffffffu, ps0, 2);
        ps1 += __shfl_xor_sync(0xffffffffu, ps1, 1);
        ps1 += __shfl_xor_sync(0xffffffffu, ps1, 2);
        l0 = l0*rs0 + ps0;
        l1 = l1*rs1 + ps1;

        // rescale O
        #pragma unroll
        for (int nf = 0; nf < 4; nf++) {
            o[nf][0] *= rs0; o[nf][1] *= rs0;
            o[nf][2] *= rs1; o[nf][3] *= rs1;
        }

        // ---- O += P.V  (P C-frag -> A-frag via shfl; V B-frags from smem)
        const int srcA = (lane & ~3) | (tg >> 1);
        const int srcB = srcA + 2;
        const bool odd = (tg & 1);
        #pragma unroll
        for (int kc = 0; kc < 4; kc++) {   // key chunk (= S n-chunk)
            float v0a = __shfl_sync(0xffffffffu, sc[kc][0], srcA);
            float v1a = __shfl_sync(0xffffffffu, sc[kc][1], srcA);
            float v2a = __shfl_sync(0xffffffffu, sc[kc][2], srcA);
            float v3a = __shfl_sync(0xffffffffu, sc[kc][3], srcA);
            float v0b = __shfl_sync(0xffffffffu, sc[kc][0], srcB);
            float v1b = __shfl_sync(0xffffffffu, sc[kc][1], srcB);
            float v2b = __shfl_sync(0xffffffffu, sc[kc][2], srcB);
            float v3b = __shfl_sync(0xffffffffu, sc[kc][3], srcB);
            unsigned aP0 = cvt_tf32(odd ? v1a : v0a);   // (g,    k=tg)
            unsigned aP1 = cvt_tf32(odd ? v3a : v2a);   // (g+8,  k=tg)
            unsigned aP2 = cvt_tf32(odd ? v1b : v0b);   // (g,    k=tg+4)
            unsigned aP3 = cvt_tf32(odd ? v3b : v2b);   // (g+8,  k=tg+4)
            #pragma unroll
            for (int nf = 0; nf < 4; nf++) {   // d chunk
                const float* vr = Vs + (kc*8 + tg)*40 + nf*8 + g;
                unsigned b0 = __float_as_uint(vr[0]);
                unsigned b1 = __float_as_uint(vr[4*40]);
                mma_tf32(o[nf][0], o[nf][1], o[nf][2], o[nf][3], aP0, aP1, aP2, aP3, b0, b1);
            }
        }
    }

    // epilogue: O /= l, query-mask (mask==0 rows zeroed), write g_head
    const float* mrow = mask + (size_t)b*L_;
    float qm0 = mrow[q0 + g], qm1 = mrow[q0 + g + 8];
    float i0 = (qm0 > 0.5f) ? (1.f/l0) : 0.f;
    float i1 = (qm1 > 0.5f) ? (1.f/l1) : 0.f;
    float* h0 = g_head + ((size_t)b*L_ + q0 + g)*DM + h*DK;
    float* h1 = g_head + ((size_t)b*L_ + q0 + g + 8)*DM + h*DK;
    #pragma unroll
    for (int nf = 0; nf < 4; nf++) {
        int col = nf*8 + 2*tg;
        *(float2*)(h0 + col) = make_float2(o[nf][0]*i0, o[nf][1]*i0);
        *(float2*)(h1 + col) = make_float2(o[nf][2]*i1, o[nf][3]*i1);
    }
}

// ---------------------------------------------------------------------------
// Kernel 3: out = (head @ Wo)^T. grid (L/32, B), 256 threads.
// ---------------------------------------------------------------------------
__global__ __launch_bounds__(256) void outproj_kernel(const float* __restrict__ Wo,
                                                      float* __restrict__ out) {
    __shared__ float Hs[32*129];
    __shared__ __align__(16) float Wos[32*128];
    const int t = threadIdx.x;
    const int l0 = blockIdx.x*32;
    const int b = blockIdx.y;

    const float* hsrc = g_head + ((size_t)b*L_ + l0)*DM;
    #pragma unroll
    for (int i = 0; i < 16; i++) {
        int idx = t + i*256;
        Hs[(idx >> 7)*129 + (idx & 127)] = hsrc[idx];
    }

    const int l = t & 31, dbase = (t >> 5) * 16;
    ull acc[8];
    #pragma unroll
    for (int i = 0; i < 8; i++) acc[i] = 0ull;
    const ull* W2 = (const ull*)Wos;

    for (int ccb = 0; ccb < 4; ccb++) {
        __syncthreads();
        #pragma unroll
        for (int i = 0; i < 16; i++) Wos[t + i*256] = Wo[ccb*32*128 + t + i*256];
        __syncthreads();
        #pragma unroll 8
        for (int j = 0; j < 32; j++) {
            float hv = Hs[l*129 + ccb*32 + j];
            ull hh = pack2(hv, hv);
            const ull* wrow = W2 + j*64 + (dbase >> 1);
            #pragma unroll
            for (int i = 0; i < 8; i++) FFMA2(acc[i], hh, wrow[i]);
        }
    }

    #pragma unroll
    for (int i = 0; i < 8; i++) {
        float lo, hi; unpack2(acc[i], lo, hi);
        int d0 = dbase + 2*i;
        out[((size_t)b*DM + d0    )*L_ + l0 + l] = lo;
        out[((size_t)b*DM + d0 + 1)*L_ + l0 + l] = hi;
    }
}

extern "C" void kernel_launch(void* const* d_in, const int* in_sizes, int n_in,
                              void* d_out, int out_size) {
    const float* x    = (const float*)d_in[0];
    const float* mask = (const float*)d_in[1];
    const float* Wq   = (const float*)d_in[2];
    const float* Wk   = (const float*)d_in[3];
    const float* Wv   = (const float*)d_in[4];
    const float* Wo   = (const float*)d_in[5];
    float* out = (float*)d_out;

    qkv_kernel<<<dim3(L_/128, B_, 12), 128>>>(x, Wq, Wk, Wv);
    attn_kernel<<<dim3(L_/64, NH, B_), 128>>>(mask);
    outproj_kernel<<<dim3(L_/32, B_), 256>>>(Wo, out);
}

// round 9
// speedup vs baseline: 2.9674x; 1.1038x over previous
#include <cuda_runtime.h>
#include <cstdint>

#define B_  8
#define L_  2048
#define DM  128
#define NH  4
#define DK  32

typedef unsigned long long ull;

// Scratch (allocation-free rule: __device__ globals)
__device__ float g_Q[B_*NH*L_*DK];   // tf32-rounded
__device__ float g_K[B_*NH*L_*DK];   // tf32-rounded
__device__ float g_V[B_*NH*L_*DK];   // tf32-rounded
__device__ float g_head[B_*L_*DM];

__device__ __forceinline__ ull pack2(float lo, float hi) {
    ull r; asm("mov.b64 %0, {%1, %2};" : "=l"(r) : "f"(lo), "f"(hi)); return r;
}
__device__ __forceinline__ void unpack2(ull v, float &lo, float &hi) {
    asm("mov.b64 {%0, %1}, %2;" : "=f"(lo), "=f"(hi) : "l"(v));
}
#define FFMA2(d,a,b) asm("fma.rn.f32x2 %0, %1, %2, %0;" : "+l"(d) : "l"(a), "l"(b))
#define FMUL2(d,a,b) asm("mul.rn.f32x2 %0, %1, %2;" : "=l"(d) : "l"(a), "l"(b))

__device__ __forceinline__ unsigned cvt_tf32(float f) {
    unsigned u; asm("cvt.rna.tf32.f32 %0, %1;" : "=r"(u) : "f"(f)); return u;
}

// cp.async 16B: gmem -> smem, register-free
#define CP_ASYNC16(dst_u32, src_ptr) \
    asm volatile("cp.async.ca.shared.global [%0], [%1], 16;" :: "r"(dst_u32), "l"(src_ptr))
#define CP_COMMIT()  asm volatile("cp.async.commit_group;")
#define CP_WAIT0()   asm volatile("cp.async.wait_group 0;")

// D += A(m16k8,tf32) * B(k8n8,tf32), fp32 accumulate
__device__ __forceinline__ void mma_tf32(float& c0, float& c1, float& c2, float& c3,
                                         unsigned a0, unsigned a1, unsigned a2, unsigned a3,
                                         unsigned b0, unsigned b1) {
    asm("mma.sync.aligned.m16n8k8.row.col.f32.tf32.tf32.f32 "
        "{%0,%1,%2,%3}, {%4,%5,%6,%7}, {%8,%9}, {%0,%1,%2,%3};"
        : "+f"(c0), "+f"(c1), "+f"(c2), "+f"(c3)
        : "r"(a0), "r"(a1), "r"(a2), "r"(a3), "r"(b0), "r"(b1));
}

// ---------------------------------------------------------------------------
// Kernel 1: QKV projection. W read as float4 (LDS.128) -> half the L1 issue
// count of the previous LDS.64 version (profile showed L1=73.6% binding).
// ---------------------------------------------------------------------------
__global__ __launch_bounds__(128) void qkv_kernel(const float* __restrict__ x,
                                                  const float* __restrict__ Wq,
                                                  const float* __restrict__ Wk,
                                                  const float* __restrict__ Wv) {
    __shared__ __align__(16) float Ws[DM*DK];
    const int t = threadIdx.x;
    const int l = blockIdx.x*128 + t;
    const int b = blockIdx.y;
    const int c = blockIdx.z;
    const int matsel = c >> 2, h = c & 3;

    const float* Wbase = (matsel==0 ? Wq : (matsel==1 ? Wk : Wv)) + h*DM*DK;
    #pragma unroll
    for (int i = 0; i < 32; i++) Ws[t + i*128] = Wbase[t + i*128];
    __syncthreads();

    const float4* W4 = (const float4*)Ws;
    ull acc[16];
    #pragma unroll
    for (int jp = 0; jp < 16; jp++) acc[jp] = 0ull;

    const float* xcol = x + (size_t)b*DM*L_ + l;
    #pragma unroll 4
    for (int d = 0; d < DM; d++) {
        float xv = __ldg(xcol + (size_t)d*L_);
        ull xp = pack2(xv, xv);
        const float4* wrow = W4 + d*8;          // 8x LDS.128 per d (was 16x LDS.64)
        #pragma unroll
        for (int q = 0; q < 8; q++) {
            float4 wv = wrow[q];
            FFMA2(acc[2*q],   xp, pack2(wv.x, wv.y));
            FFMA2(acc[2*q+1], xp, pack2(wv.z, wv.w));
        }
    }

    const float sc = (matsel == 0) ? 0.17677669529663687f : 1.0f;  // 1/sqrt(32) into Q
    float* dst = (matsel==0 ? g_Q : (matsel==1 ? g_K : g_V)) + (((size_t)b*NH + h)*L_ + l)*DK;
    #pragma unroll
    for (int jp = 0; jp < 16; jp++) {
        float lo, hi; unpack2(acc[jp], lo, hi);
        dst[2*jp]   = __uint_as_float(cvt_tf32(lo*sc));
        dst[2*jp+1] = __uint_as_float(cvt_tf32(hi*sc));
    }
}

// ---------------------------------------------------------------------------
// Kernel 2: flash attention, tf32 mma.sync, 64-key tiles, cp.async double
// buffer. grid (L/64, NH, B), 128 threads = 4 warps, warp owns m16 q-rows.
// ---------------------------------------------------------------------------
__global__ __launch_bounds__(128) void attn_kernel(const float* __restrict__ mask) {
    __shared__ __align__(16) float Ks[2][64*36];
    __shared__ __align__(16) float Vs[2][64*40];
    __shared__ __align__(16) float msk[2][64];

    const int t = threadIdx.x;
    const int lane = t & 31, w = t >> 5;
    const int g = lane >> 2, tg = lane & 3;
    const int h = blockIdx.y, b = blockIdx.z;
    const size_t bh = (size_t)b*NH + h;
    const int q0 = blockIdx.x*64 + w*16;

    // Q fragments (tf32-rounded in memory)
    unsigned aQ[4][4];
    const float* Qb = g_Q + (bh*L_ + q0)*DK;
    #pragma unroll
    for (int kc = 0; kc < 4; kc++) {
        int d0 = kc*8 + tg;
        aQ[kc][0] = __float_as_uint(Qb[(size_t)g*DK + d0]);
        aQ[kc][1] = __float_as_uint(Qb[(size_t)(g+8)*DK + d0]);
        aQ[kc][2] = __float_as_uint(Qb[(size_t)g*DK + d0 + 4]);
        aQ[kc][3] = __float_as_uint(Qb[(size_t)(g+8)*DK + d0 + 4]);
    }

    float o[4][4];
    #pragma unroll
    for (int i = 0; i < 4; i++)
        #pragma unroll
        for (int j = 0; j < 4; j++) o[i][j] = 0.f;
    float m0 = -1e30f, m1 = -1e30f, l0 = 0.f, l1 = 0.f;

    const float4* K4 = (const float4*)(g_K + bh*L_*DK);
    const float4* V4 = (const float4*)(g_V + bh*L_*DK);
    const float*  mrowg = mask + (size_t)b*L_;

    // per-thread float4 slots: f = t + 128*i, row = f>>3, col4 = (f&7)*4
    // issue tile -> smem[buf] via cp.async (16B; row strides 144B/160B are 16B-aligned)
    auto issue_tile = [&](int kt, int buf) {
        #pragma unroll
        for (int i = 0; i < 4; i++) {
            int f = t + 128*i;
            int row = f >> 3, col = (f & 7) * 4;
            unsigned kd = (unsigned)__cvta_generic_to_shared(&Ks[buf][row*36 + col]);
            unsigned vd = (unsigned)__cvta_generic_to_shared(&Vs[buf][row*40 + col]);
            CP_ASYNC16(kd, K4 + kt*512 + f);
            CP_ASYNC16(vd, V4 + kt*512 + f);
        }
        if (t < 16) {
            unsigned md = (unsigned)__cvta_generic_to_shared(&msk[buf][t*4]);
            CP_ASYNC16(md, mrowg + kt*64 + t*4);
        }
        CP_COMMIT();
    };

    issue_tile(0, 0);

    const int NT = L_/64;
    for (int kt = 0; kt < NT; kt++) {
        const int buf = kt & 1;
        CP_WAIT0();
        __syncthreads();                       // tile kt ready; all warps done with buf^1
        if (kt + 1 < NT) issue_tile(kt + 1, buf ^ 1);

        const float* Kb = Ks[buf];
        const float* Vb = Vs[buf];
        const float* mk = msk[buf];

        // ---- S = Q.K^T : 8 n-chunks x 4 k-chunks of m16n8k8
        float sc[8][4];
        #pragma unroll
        for (int nf = 0; nf < 8; nf++) {
            float c0 = 0.f, c1 = 0.f, c2 = 0.f, c3 = 0.f;
            #pragma unroll
            for (int kc = 0; kc < 4; kc++) {
                const float* kr = Kb + (nf*8 + g)*36 + kc*8 + tg;
                unsigned b0 = __float_as_uint(kr[0]);
                unsigned b1 = __float_as_uint(kr[4]);
                mma_tf32(c0, c1, c2, c3, aQ[kc][0], aQ[kc][1], aQ[kc][2], aQ[kc][3], b0, b1);
            }
            sc[nf][0] = c0; sc[nf][1] = c1; sc[nf][2] = c2; sc[nf][3] = c3;
        }

        // ---- key mask (mask==1 keys -> -1e30)
        const int k2 = 2*tg;
        #pragma unroll
        for (int nf = 0; nf < 8; nf++) {
            float mk0 = mk[nf*8 + k2], mk1 = mk[nf*8 + k2 + 1];
            if (mk0 > 0.5f) { sc[nf][0] = -1e30f; sc[nf][2] = -1e30f; }
            if (mk1 > 0.5f) { sc[nf][1] = -1e30f; sc[nf][3] = -1e30f; }
        }

        // ---- online softmax (rows g and g+8)
        float tm0 = -1e30f, tm1 = -1e30f;
        #pragma unroll
        for (int nf = 0; nf < 8; nf++) {
            tm0 = fmaxf(tm0, fmaxf(sc[nf][0], sc[nf][1]));
            tm1 = fmaxf(tm1, fmaxf(sc[nf][2], sc[nf][3]));
        }
        tm0 = fmaxf(tm0, __shfl_xor_sync(0xffffffffu, tm0, 1));
        tm0 = fmaxf(tm0, __shfl_xor_sync(0xffffffffu, tm0, 2));
        tm1 = fmaxf(tm1, __shfl_xor_sync(0xffffffffu, tm1, 1));
        tm1 = fmaxf(tm1, __shfl_xor_sync(0xffffffffu, tm1, 2));

        float mn0 = fmaxf(m0, tm0), mn1 = fmaxf(m1, tm1);
        float rs0 = __expf(m0 - mn0), rs1 = __expf(m1 - mn1);
        m0 = mn0; m1 = mn1;

        float ps0 = 0.f, ps1 = 0.f;
        #pragma unroll
        for (int nf = 0; nf < 8; nf++) {
            sc[nf][0] = __expf(sc[nf][0] - mn0);
            sc[nf][1] = __expf(sc[nf][1] - mn0);
            sc[nf][2] = __expf(sc[nf][2] - mn1);
            sc[nf][3] = __expf(sc[nf][3] - mn1);
            ps0 += sc[nf][0] + sc[nf][1];
            ps1 += sc[nf][2] + sc[nf][3];
        }
        ps0 += __shfl_xor_sync(0xffffffffu, ps0, 1);
        ps0 += __shfl_xor_sync(0xffffffffu, ps0, 2);
        ps1 += __shfl_xor_sync(0xffffffffu, ps1, 1);
        ps1 += __shfl_xor_sync(0xffffffffu, ps1, 2);
        l0 = l0*rs0 + ps0;
        l1 = l1*rs1 + ps1;

        #pragma unroll
        for (int nf = 0; nf < 4; nf++) {
            o[nf][0] *= rs0; o[nf][1] *= rs0;
            o[nf][2] *= rs1; o[nf][3] *= rs1;
        }

        // ---- O += P.V  (P C-frag -> A-frag via shfl; V B-frags from smem)
        const int srcA = (lane & ~3) | (tg >> 1);
        const int srcB = srcA + 2;
        const bool odd = (tg & 1);
        #pragma unroll
        for (int kc = 0; kc < 8; kc++) {   // key chunk (= S n-chunk)
            float v0a = __shfl_sync(0xffffffffu, sc[kc][0], srcA);
            float v1a = __shfl_sync(0xffffffffu, sc[kc][1], srcA);
            float v2a = __shfl_sync(0xffffffffu, sc[kc][2], srcA);
            float v3a = __shfl_sync(0xffffffffu, sc[kc][3], srcA);
            float v0b = __shfl_sync(0xffffffffu, sc[kc][0], srcB);
            float v1b = __shfl_sync(0xffffffffu, sc[kc][1], srcB);
            float v2b = __shfl_sync(0xffffffffu, sc[kc][2], srcB);
            float v3b = __shfl_sync(0xffffffffu, sc[kc][3], srcB);
            unsigned aP0 = cvt_tf32(odd ? v1a : v0a);   // (g,    k=tg)
            unsigned aP1 = cvt_tf32(odd ? v3a : v2a);   // (g+8,  k=tg)
            unsigned aP2 = cvt_tf32(odd ? v1b : v0b);   // (g,    k=tg+4)
            unsigned aP3 = cvt_tf32(odd ? v3b : v2b);   // (g+8,  k=tg+4)
            #pragma unroll
            for (int nf = 0; nf < 4; nf++) {   // d chunk
                const float* vr = Vb + (kc*8 + tg)*40 + nf*8 + g;
                unsigned b0 = __float_as_uint(vr[0]);
                unsigned b1 = __float_as_uint(vr[4*40]);
                mma_tf32(o[nf][0], o[nf][1], o[nf][2], o[nf][3], aP0, aP1, aP2, aP3, b0, b1);
            }
        }
        __syncthreads();                       // all warps done with buf before next overwrite
    }

    // epilogue: O /= l, query-mask (mask==0 rows zeroed), write g_head
    float qm0 = mrowg[q0 + g], qm1 = mrowg[q0 + g + 8];
    float i0 = (qm0 > 0.5f) ? (1.f/l0) : 0.f;
    float i1 = (qm1 > 0.5f) ? (1.f/l1) : 0.f;
    float* h0 = g_head + ((size_t)b*L_ + q0 + g)*DM + h*DK;
    float* h1 = g_head + ((size_t)b*L_ + q0 + g + 8)*DM + h*DK;
    #pragma unroll
    for (int nf = 0; nf < 4; nf++) {
        int col = nf*8 + 2*tg;
        *(float2*)(h0 + col) = make_float2(o[nf][0]*i0, o[nf][1]*i0);
        *(float2*)(h1 + col) = make_float2(o[nf][2]*i1, o[nf][3]*i1);
    }
}

// ---------------------------------------------------------------------------
// Kernel 3: out = (head @ Wo)^T. grid (L/32, B), 256 threads.
// ---------------------------------------------------------------------------
__global__ __launch_bounds__(256) void outproj_kernel(const float* __restrict__ Wo,
                                                      float* __restrict__ out) {
    __shared__ float Hs[32*129];
    __shared__ __align__(16) float Wos[32*128];
    const int t = threadIdx.x;
    const int l0 = blockIdx.x*32;
    const int b = blockIdx.y;

    const float* hsrc = g_head + ((size_t)b*L_ + l0)*DM;
    #pragma unroll
    for (int i = 0; i < 16; i++) {
        int idx = t + i*256;
        Hs[(idx >> 7)*129 + (idx & 127)] = hsrc[idx];
    }

    const int l = t & 31, dbase = (t >> 5) * 16;
    ull acc[8];
    #pragma unroll
    for (int i = 0; i < 8; i++) acc[i] = 0ull;
    const ull* W2 = (const ull*)Wos;

    for (int ccb = 0; ccb < 4; ccb++) {
        __syncthreads();
        #pragma unroll
        for (int i = 0; i < 16; i++) Wos[t + i*256] = Wo[ccb*32*128 + t + i*256];
        __syncthreads();
        #pragma unroll 8
        for (int j = 0; j < 32; j++) {
            float hv = Hs[l*129 + ccb*32 + j];
            ull hh = pack2(hv, hv);
            const ull* wrow = W2 + j*64 + (dbase >> 1);
            #pragma unroll
            for (int i = 0; i < 8; i++) FFMA2(acc[i], hh, wrow[i]);
        }
    }

    #pragma unroll
    for (int i = 0; i < 8; i++) {
        float lo, hi; unpack2(acc[i], lo, hi);
        int d0 = dbase + 2*i;
        out[((size_t)b*DM + d0    )*L_ + l0 + l] = lo;
        out[((size_t)b*DM + d0 + 1)*L_ + l0 + l] = hi;
    }
}

extern "C" void kernel_launch(void* const* d_in, const int* in_sizes, int n_in,
                              void* d_out, int out_size) {
    const float* x    = (const float*)d_in[0];
    const float* mask = (const float*)d_in[1];
    const float* Wq   = (const float*)d_in[2];
    const float* Wk   = (const float*)d_in[3];
    const float* Wv   = (const float*)d_in[4];
    const float* Wo   = (const float*)d_in[5];
    float* out = (float*)d_out;

    qkv_kernel<<<dim3(L_/128, B_, 12), 128>>>(x, Wq, Wk, Wv);
    attn_kernel<<<dim3(L_/64, NH, B_), 128>>>(mask);
    outproj_kernel<<<dim3(L_/32, B_), 256>>>(Wo, out);
}

// round 10
// speedup vs baseline: 3.5554x; 1.1981x over previous
#include <cuda_runtime.h>
#include <cstdint>

#define B_  8
#define L_  2048
#define DM  128
#define NH  4
#define DK  32

typedef unsigned long long ull;

// Scratch (allocation-free rule: __device__ globals)
__device__ float g_Q[B_*NH*L_*DK];   // tf32-rounded
__device__ float g_K[B_*NH*L_*DK];   // tf32-rounded
__device__ float g_V[B_*NH*L_*DK];   // tf32-rounded
__device__ float g_head[B_*L_*DM];

__device__ __forceinline__ ull pack2(float lo, float hi) {
    ull r; asm("mov.b64 %0, {%1, %2};" : "=l"(r) : "f"(lo), "f"(hi)); return r;
}
__device__ __forceinline__ void unpack2(ull v, float &lo, float &hi) {
    asm("mov.b64 {%0, %1}, %2;" : "=f"(lo), "=f"(hi) : "l"(v));
}
#define FFMA2(d,a,b) asm("fma.rn.f32x2 %0, %1, %2, %0;" : "+l"(d) : "l"(a), "l"(b))
#define FMUL2(d,a,b) asm("mul.rn.f32x2 %0, %1, %2;" : "=l"(d) : "l"(a), "l"(b))

__device__ __forceinline__ unsigned cvt_tf32(float f) {
    unsigned u; asm("cvt.rna.tf32.f32 %0, %1;" : "=r"(u) : "f"(f)); return u;
}

// cp.async 16B: gmem -> smem, register-free
#define CP_ASYNC16(dst_u32, src_ptr) \
    asm volatile("cp.async.ca.shared.global [%0], [%1], 16;" :: "r"(dst_u32), "l"(src_ptr))
#define CP_COMMIT()  asm volatile("cp.async.commit_group;")
#define CP_WAIT0()   asm volatile("cp.async.wait_group 0;")

// D += A(m16k8,tf32) * B(k8n8,tf32), fp32 accumulate
__device__ __forceinline__ void mma_tf32(float& c0, float& c1, float& c2, float& c3,
                                         unsigned a0, unsigned a1, unsigned a2, unsigned a3,
                                         unsigned b0, unsigned b1) {
    asm("mma.sync.aligned.m16n8k8.row.col.f32.tf32.tf32.f32 "
        "{%0,%1,%2,%3}, {%4,%5,%6,%7}, {%8,%9}, {%0,%1,%2,%3};"
        : "+f"(c0), "+f"(c1), "+f"(c2), "+f"(c3)
        : "r"(a0), "r"(a1), "r"(a2), "r"(a3), "r"(b0), "r"(b1));
}

// ---------------------------------------------------------------------------
// Kernel 1: QKV projection on tf32 mma.sync.
// grid (L/64, B, 12): z = (matrix, head). 128 thr = 4 warps, warp owns m16 rows.
// A-frags (x^T rows) loaded straight from global (4x32B sectors per LDG);
// W staged transposed in smem, stride 132 -> B-frag bank index 4g+tg, conflict-free.
// ---------------------------------------------------------------------------
__global__ __launch_bounds__(128) void qkv_kernel(const float* __restrict__ x,
                                                  const float* __restrict__ Wq,
                                                  const float* __restrict__ Wk,
                                                  const float* __restrict__ Wv) {
    __shared__ float Wt[32*132];
    const int t = threadIdx.x;
    const int lane = t & 31, w = t >> 5;
    const int g = lane >> 2, tg = lane & 3;
    const int l0 = blockIdx.x*64;
    const int b = blockIdx.y;
    const int c = blockIdx.z;
    const int matsel = c >> 2, h = c & 3;

    // stage W transposed: Wt[j][d], tf32-rounded
    const float* Wbase = (matsel==0 ? Wq : (matsel==1 ? Wk : Wv)) + h*DM*DK;
    #pragma unroll
    for (int i = 0; i < 32; i++) {
        int idx = t + i*128;               // coalesced read W[d][j]
        int d = idx >> 5, j = idx & 31;
        Wt[j*132 + d] = __uint_as_float(cvt_tf32(Wbase[idx]));
    }
    __syncthreads();

    // A-frags from x (tf32-rounded): rows l0+w*16+{g,g+8}, cols kc*8+tg(+4)
    const float* xb = x + (size_t)b*DM*L_ + l0 + w*16;
    unsigned aX[16][4];
    #pragma unroll
    for (int kc = 0; kc < 16; kc++) {
        int d0 = kc*8 + tg;
        aX[kc][0] = cvt_tf32(__ldg(xb + (size_t)d0*L_ + g));
        aX[kc][1] = cvt_tf32(__ldg(xb + (size_t)d0*L_ + g + 8));
        aX[kc][2] = cvt_tf32(__ldg(xb + (size_t)(d0+4)*L_ + g));
        aX[kc][3] = cvt_tf32(__ldg(xb + (size_t)(d0+4)*L_ + g + 8));
    }

    float cq[4][4];
    #pragma unroll
    for (int i = 0; i < 4; i++)
        #pragma unroll
        for (int j = 0; j < 4; j++) cq[i][j] = 0.f;

    #pragma unroll
    for (int nf = 0; nf < 4; nf++) {
        #pragma unroll
        for (int kc = 0; kc < 16; kc++) {
            const float* wr = Wt + (nf*8 + g)*132 + kc*8 + tg;
            unsigned b0 = __float_as_uint(wr[0]);
            unsigned b1 = __float_as_uint(wr[4]);
            mma_tf32(cq[nf][0], cq[nf][1], cq[nf][2], cq[nf][3],
                     aX[kc][0], aX[kc][1], aX[kc][2], aX[kc][3], b0, b1);
        }
    }

    // epilogue: scale (Q only), tf32-round, store
    const float sc = (matsel == 0) ? 0.17677669529663687f : 1.0f;  // 1/sqrt(32) into Q
    float* dst = (matsel==0 ? g_Q : (matsel==1 ? g_K : g_V))
                 + (((size_t)b*NH + h)*L_ + l0 + w*16)*DK;
    #pragma unroll
    for (int nf = 0; nf < 4; nf++) {
        int j = nf*8 + 2*tg;
        float2 v0 = make_float2(__uint_as_float(cvt_tf32(cq[nf][0]*sc)),
                                __uint_as_float(cvt_tf32(cq[nf][1]*sc)));
        float2 v1 = make_float2(__uint_as_float(cvt_tf32(cq[nf][2]*sc)),
                                __uint_as_float(cvt_tf32(cq[nf][3]*sc)));
        *(float2*)(dst + (size_t)g*DK + j)       = v0;
        *(float2*)(dst + (size_t)(g+8)*DK + j)   = v1;
    }
}

// ---------------------------------------------------------------------------
// Kernel 2: flash attention, tf32 mma.sync, 64-key tiles, cp.async double
// buffer. grid (L/64, NH, B), 128 threads = 4 warps, warp owns m16 q-rows.
// ---------------------------------------------------------------------------
__global__ __launch_bounds__(128) void attn_kernel(const float* __restrict__ mask) {
    __shared__ __align__(16) float Ks[2][64*36];
    __shared__ __align__(16) float Vs[2][64*40];
    __shared__ __align__(16) float msk[2][64];

    const int t = threadIdx.x;
    const int lane = t & 31, w = t >> 5;
    const int g = lane >> 2, tg = lane & 3;
    const int h = blockIdx.y, b = blockIdx.z;
    const size_t bh = (size_t)b*NH + h;
    const int q0 = blockIdx.x*64 + w*16;

    // Q fragments (tf32-rounded in memory)
    unsigned aQ[4][4];
    const float* Qb = g_Q + (bh*L_ + q0)*DK;
    #pragma unroll
    for (int kc = 0; kc < 4; kc++) {
        int d0 = kc*8 + tg;
        aQ[kc][0] = __float_as_uint(Qb[(size_t)g*DK + d0]);
        aQ[kc][1] = __float_as_uint(Qb[(size_t)(g+8)*DK + d0]);
        aQ[kc][2] = __float_as_uint(Qb[(size_t)g*DK + d0 + 4]);
        aQ[kc][3] = __float_as_uint(Qb[(size_t)(g+8)*DK + d0 + 4]);
    }

    float o[4][4];
    #pragma unroll
    for (int i = 0; i < 4; i++)
        #pragma unroll
        for (int j = 0; j < 4; j++) o[i][j] = 0.f;
    float m0 = -1e30f, m1 = -1e30f, l0 = 0.f, l1 = 0.f;

    const float4* K4 = (const float4*)(g_K + bh*L_*DK);
    const float4* V4 = (const float4*)(g_V + bh*L_*DK);
    const float*  mrowg = mask + (size_t)b*L_;

    auto issue_tile = [&](int kt, int buf) {
        #pragma unroll
        for (int i = 0; i < 4; i++) {
            int f = t + 128*i;
            int row = f >> 3, col = (f & 7) * 4;
            unsigned kd = (unsigned)__cvta_generic_to_shared(&Ks[buf][row*36 + col]);
            unsigned vd = (unsigned)__cvta_generic_to_shared(&Vs[buf][row*40 + col]);
            CP_ASYNC16(kd, K4 + kt*512 + f);
            CP_ASYNC16(vd, V4 + kt*512 + f);
        }
        if (t < 16) {
            unsigned md = (unsigned)__cvta_generic_to_shared(&msk[buf][t*4]);
            CP_ASYNC16(md, mrowg + kt*64 + t*4);
        }
        CP_COMMIT();
    };

    issue_tile(0, 0);

    const int NT = L_/64;
    for (int kt = 0; kt < NT; kt++) {
        const int buf = kt & 1;
        CP_WAIT0();
        __syncthreads();
        if (kt + 1 < NT) issue_tile(kt + 1, buf ^ 1);

        const float* Kb = Ks[buf];
        const float* Vb = Vs[buf];
        const float* mk = msk[buf];

        // ---- S = Q.K^T : 8 n-chunks x 4 k-chunks of m16n8k8
        float sc[8][4];
        #pragma unroll
        for (int nf = 0; nf < 8; nf++) {
            float c0 = 0.f, c1 = 0.f, c2 = 0.f, c3 = 0.f;
            #pragma unroll
            for (int kc = 0; kc < 4; kc++) {
                const float* kr = Kb + (nf*8 + g)*36 + kc*8 + tg;
                unsigned b0 = __float_as_uint(kr[0]);
                unsigned b1 = __float_as_uint(kr[4]);
                mma_tf32(c0, c1, c2, c3, aQ[kc][0], aQ[kc][1], aQ[kc][2], aQ[kc][3], b0, b1);
            }
            sc[nf][0] = c0; sc[nf][1] = c1; sc[nf][2] = c2; sc[nf][3] = c3;
        }

        // ---- key mask (mask==1 keys -> -1e30)
        const int k2 = 2*tg;
        #pragma unroll
        for (int nf = 0; nf < 8; nf++) {
            float mk0 = mk[nf*8 + k2], mk1 = mk[nf*8 + k2 + 1];
            if (mk0 > 0.5f) { sc[nf][0] = -1e30f; sc[nf][2] = -1e30f; }
            if (mk1 > 0.5f) { sc[nf][1] = -1e30f; sc[nf][3] = -1e30f; }
        }

        // ---- online softmax (rows g and g+8)
        float tm0 = -1e30f, tm1 = -1e30f;
        #pragma unroll
        for (int nf = 0; nf < 8; nf++) {
            tm0 = fmaxf(tm0, fmaxf(sc[nf][0], sc[nf][1]));
            tm1 = fmaxf(tm1, fmaxf(sc[nf][2], sc[nf][3]));
        }
        tm0 = fmaxf(tm0, __shfl_xor_sync(0xffffffffu, tm0, 1));
        tm0 = fmaxf(tm0, __shfl_xor_sync(0xffffffffu, tm0, 2));
        tm1 = fmaxf(tm1, __shfl_xor_sync(0xffffffffu, tm1, 1));
        tm1 = fmaxf(tm1, __shfl_xor_sync(0xffffffffu, tm1, 2));

        float mn0 = fmaxf(m0, tm0), mn1 = fmaxf(m1, tm1);
        float rs0 = __expf(m0 - mn0), rs1 = __expf(m1 - mn1);
        m0 = mn0; m1 = mn1;

        float ps0 = 0.f, ps1 = 0.f;
        #pragma unroll
        for (int nf = 0; nf < 8; nf++) {
            sc[nf][0] = __expf(sc[nf][0] - mn0);
            sc[nf][1] = __expf(sc[nf][1] - mn0);
            sc[nf][2] = __expf(sc[nf][2] - mn1);
            sc[nf][3] = __expf(sc[nf][3] - mn1);
            ps0 += sc[nf][0] + sc[nf][1];
            ps1 += sc[nf][2] + sc[nf][3];
        }
        ps0 += __shfl_xor_sync(0xffffffffu, ps0, 1);
        ps0 += __shfl_xor_sync(0xffffffffu, ps0, 2);
        ps1 += __shfl_xor_sync(0xffffffffu, ps1, 1);
        ps1 += __shfl_xor_sync(0xffffffffu, ps1, 2);
        l0 = l0*rs0 + ps0;
        l1 = l1*rs1 + ps1;

        #pragma unroll
        for (int nf = 0; nf < 4; nf++) {
            o[nf][0] *= rs0; o[nf][1] *= rs0;
            o[nf][2] *= rs1; o[nf][3] *= rs1;
        }

        // ---- O += P.V
        const int srcA = (lane & ~3) | (tg >> 1);
        const int srcB = srcA + 2;
        const bool odd = (tg & 1);
        #pragma unroll
        for (int kc = 0; kc < 8; kc++) {
            float v0a = __shfl_sync(0xffffffffu, sc[kc][0], srcA);
            float v1a = __shfl_sync(0xffffffffu, sc[kc][1], srcA);
            float v2a = __shfl_sync(0xffffffffu, sc[kc][2], srcA);
            float v3a = __shfl_sync(0xffffffffu, sc[kc][3], srcA);
            float v0b = __shfl_sync(0xffffffffu, sc[kc][0], srcB);
            float v1b = __shfl_sync(0xffffffffu, sc[kc][1], srcB);
            float v2b = __shfl_sync(0xffffffffu, sc[kc][2], srcB);
            float v3b = __shfl_sync(0xffffffffu, sc[kc][3], srcB);
            unsigned aP0 = cvt_tf32(odd ? v1a : v0a);
            unsigned aP1 = cvt_tf32(odd ? v3a : v2a);
            unsigned aP2 = cvt_tf32(odd ? v1b : v0b);
            unsigned aP3 = cvt_tf32(odd ? v3b : v2b);
            #pragma unroll
            for (int nf = 0; nf < 4; nf++) {
                const float* vr = Vb + (kc*8 + tg)*40 + nf*8 + g;
                unsigned b0 = __float_as_uint(vr[0]);
                unsigned b1 = __float_as_uint(vr[4*40]);
                mma_tf32(o[nf][0], o[nf][1], o[nf][2], o[nf][3], aP0, aP1, aP2, aP3, b0, b1);
            }
        }
        __syncthreads();
    }

    // epilogue: O /= l, query-mask (mask==0 rows zeroed), write g_head
    float qm0 = mrowg[q0 + g], qm1 = mrowg[q0 + g + 8];
    float i0 = (qm0 > 0.5f) ? (1.f/l0) : 0.f;
    float i1 = (qm1 > 0.5f) ? (1.f/l1) : 0.f;
    float* h0 = g_head + ((size_t)b*L_ + q0 + g)*DM + h*DK;
    float* h1 = g_head + ((size_t)b*L_ + q0 + g + 8)*DM + h*DK;
    #pragma unroll
    for (int nf = 0; nf < 4; nf++) {
        int col = nf*8 + 2*tg;
        *(float2*)(h0 + col) = make_float2(o[nf][0]*i0, o[nf][1]*i0);
        *(float2*)(h1 + col) = make_float2(o[nf][2]*i1, o[nf][3]*i1);
    }
}

// ---------------------------------------------------------------------------
// Kernel 3: out = (head @ Wo)^T. grid (L/32, B), 256 threads.
// ---------------------------------------------------------------------------
__global__ __launch_bounds__(256) void outproj_kernel(const float* __restrict__ Wo,
                                                      float* __restrict__ out) {
    __shared__ float Hs[32*129];
    __shared__ __align__(16) float Wos[32*128];
    const int t = threadIdx.x;
    const int l0 = blockIdx.x*32;
    const int b = blockIdx.y;

    const float* hsrc = g_head + ((size_t)b*L_ + l0)*DM;
    #pragma unroll
    for (int i = 0; i < 16; i++) {
        int idx = t + i*256;
        Hs[(idx >> 7)*129 + (idx & 127)] = hsrc[idx];
    }

    const int l = t & 31, dbase = (t >> 5) * 16;
    ull acc[8];
    #pragma unroll
    for (int i = 0; i < 8; i++) acc[i] = 0ull;
    const ull* W2 = (const ull*)Wos;

    for (int ccb = 0; ccb < 4; ccb++) {
        __syncthreads();
        #pragma unroll
        for (int i = 0; i < 16; i++) Wos[t + i*256] = Wo[ccb*32*128 + t + i*256];
        __syncthreads();
        #pragma unroll 8
        for (int j = 0; j < 32; j++) {
            float hv = Hs[l*129 + ccb*32 + j];
            ull hh = pack2(hv, hv);
            const ull* wrow = W2 + j*64 + (dbase >> 1);
            #pragma unroll
            for (int i = 0; i < 8; i++) FFMA2(acc[i], hh, wrow[i]);
        }
    }

    #pragma unroll
    for (int i = 0; i < 8; i++) {
        float lo, hi; unpack2(acc[i], lo, hi);
        int d0 = dbase + 2*i;
        out[((size_t)b*DM + d0    )*L_ + l0 + l] = lo;
        out[((size_t)b*DM + d0 + 1)*L_ + l0 + l] = hi;
    }
}

extern "C" void kernel_launch(void* const* d_in, const int* in_sizes, int n_in,
                              void* d_out, int out_size) {
    const float* x    = (const float*)d_in[0];
    const float* mask = (const float*)d_in[1];
    const float* Wq   = (const float*)d_in[2];
    const float* Wk   = (const float*)d_in[3];
    const float* Wv   = (const float*)d_in[4];
    const float* Wo   = (const float*)d_in[5];
    float* out = (float*)d_out;

    qkv_kernel<<<dim3(L_/64, B_, 12), 128>>>(x, Wq, Wk, Wv);
    attn_kernel<<<dim3(L_/64, NH, B_), 128>>>(mask);
    outproj_kernel<<<dim3(L_/32, B_), 256>>>(Wo, out);
}

// round 12
// speedup vs baseline: 3.7414x; 1.0523x over previous
#include <cuda_runtime.h>
#include <cstdint>

#define B_  8
#define L_  2048
#define DM  128
#define NH  4
#define DK  32

typedef unsigned long long ull;

// Scratch (allocation-free rule: __device__ globals)
__device__ float g_Q[B_*NH*L_*DK];   // tf32-rounded
__device__ float g_K[B_*NH*L_*DK];   // tf32-rounded
__device__ float g_V[B_*NH*L_*DK];   // tf32-rounded
__device__ float g_head[B_*L_*DM];

__device__ __forceinline__ unsigned cvt_tf32(float f) {
    unsigned u; asm("cvt.rna.tf32.f32 %0, %1;" : "=r"(u) : "f"(f)); return u;
}

// cp.async 16B: gmem -> smem, register-free
#define CP_ASYNC16(dst_u32, src_ptr) \
    asm volatile("cp.async.ca.shared.global [%0], [%1], 16;" :: "r"(dst_u32), "l"(src_ptr))
#define CP_COMMIT()  asm volatile("cp.async.commit_group;")
#define CP_WAIT0()   asm volatile("cp.async.wait_group 0;")

// D += A(m16k8,tf32) * B(k8n8,tf32), fp32 accumulate
__device__ __forceinline__ void mma_tf32(float& c0, float& c1, float& c2, float& c3,
                                         unsigned a0, unsigned a1, unsigned a2, unsigned a3,
                                         unsigned b0, unsigned b1) {
    asm("mma.sync.aligned.m16n8k8.row.col.f32.tf32.tf32.f32 "
        "{%0,%1,%2,%3}, {%4,%5,%6,%7}, {%8,%9}, {%0,%1,%2,%3};"
        : "+f"(c0), "+f"(c1), "+f"(c2), "+f"(c3)
        : "r"(a0), "r"(a1), "r"(a2), "r"(a3), "r"(b0), "r"(b1));
}

// ---------------------------------------------------------------------------
// Kernel 1: QKV projection on tf32 mma.sync.
// grid (L/64, B, 12): z = (matrix, head). 128 thr = 4 warps, warp owns m16 rows.
// ---------------------------------------------------------------------------
__global__ __launch_bounds__(128) void qkv_kernel(const float* __restrict__ x,
                                                  const float* __restrict__ Wq,
                                                  const float* __restrict__ Wk,
                                                  const float* __restrict__ Wv) {
    __shared__ float Wt[32*132];
    const int t = threadIdx.x;
    const int lane = t & 31, w = t >> 5;
    const int g = lane >> 2, tg = lane & 3;
    const int l0 = blockIdx.x*64;
    const int b = blockIdx.y;
    const int c = blockIdx.z;
    const int matsel = c >> 2, h = c & 3;

    // stage W transposed: Wt[j][d], tf32-rounded
    const float* Wbase = (matsel==0 ? Wq : (matsel==1 ? Wk : Wv)) + h*DM*DK;
    #pragma unroll
    for (int i = 0; i < 32; i++) {
        int idx = t + i*128;               // coalesced read W[d][j]
        int d = idx >> 5, j = idx & 31;
        Wt[j*132 + d] = __uint_as_float(cvt_tf32(Wbase[idx]));
    }
    __syncthreads();

    // A-frags from x (tf32-rounded): rows l0+w*16+{g,g+8}, cols kc*8+tg(+4)
    const float* xb = x + (size_t)b*DM*L_ + l0 + w*16;
    unsigned aX[16][4];
    #pragma unroll
    for (int kc = 0; kc < 16; kc++) {
        int d0 = kc*8 + tg;
        aX[kc][0] = cvt_tf32(__ldg(xb + (size_t)d0*L_ + g));
        aX[kc][1] = cvt_tf32(__ldg(xb + (size_t)d0*L_ + g + 8));
        aX[kc][2] = cvt_tf32(__ldg(xb + (size_t)(d0+4)*L_ + g));
        aX[kc][3] = cvt_tf32(__ldg(xb + (size_t)(d0+4)*L_ + g + 8));
    }

    float cq[4][4];
    #pragma unroll
    for (int i = 0; i < 4; i++)
        #pragma unroll
        for (int j = 0; j < 4; j++) cq[i][j] = 0.f;

    #pragma unroll
    for (int nf = 0; nf < 4; nf++) {
        #pragma unroll
        for (int kc = 0; kc < 16; kc++) {
            const float* wr = Wt + (nf*8 + g)*132 + kc*8 + tg;
            unsigned b0 = __float_as_uint(wr[0]);
            unsigned b1 = __float_as_uint(wr[4]);
            mma_tf32(cq[nf][0], cq[nf][1], cq[nf][2], cq[nf][3],
                     aX[kc][0], aX[kc][1], aX[kc][2], aX[kc][3], b0, b1);
        }
    }

    // epilogue: scale (Q only), tf32-round, store
    const float sc = (matsel == 0) ? 0.17677669529663687f : 1.0f;  // 1/sqrt(32) into Q
    float* dst = (matsel==0 ? g_Q : (matsel==1 ? g_K : g_V))
                 + (((size_t)b*NH + h)*L_ + l0 + w*16)*DK;
    #pragma unroll
    for (int nf = 0; nf < 4; nf++) {
        int j = nf*8 + 2*tg;
        float2 v0 = make_float2(__uint_as_float(cvt_tf32(cq[nf][0]*sc)),
                                __uint_as_float(cvt_tf32(cq[nf][1]*sc)));
        float2 v1 = make_float2(__uint_as_float(cvt_tf32(cq[nf][2]*sc)),
                                __uint_as_float(cvt_tf32(cq[nf][3]*sc)));
        *(float2*)(dst + (size_t)g*DK + j)       = v0;
        *(float2*)(dst + (size_t)(g+8)*DK + j)   = v1;
    }
}

// ---------------------------------------------------------------------------
// Kernel 2: flash attention, tf32 mma.sync, 64-key tiles, cp.async double
// buffer, single barrier per tile. grid (L/64, NH, B), 128 threads = 4 warps.
// ---------------------------------------------------------------------------
__global__ __launch_bounds__(128) void attn_kernel(const float* __restrict__ mask) {
    __shared__ __align__(16) float Ks[2][64*36];
    __shared__ __align__(16) float Vs[2][64*40];
    __shared__ __align__(16) float msk[2][64];

    const int t = threadIdx.x;
    const int lane = t & 31, w = t >> 5;
    const int g = lane >> 2, tg = lane & 3;
    const int h = blockIdx.y, b = blockIdx.z;
    const size_t bh = (size_t)b*NH + h;
    const int q0 = blockIdx.x*64 + w*16;

    // Q fragments (tf32-rounded in memory)
    unsigned aQ[4][4];
    const float* Qb = g_Q + (bh*L_ + q0)*DK;
    #pragma unroll
    for (int kc = 0; kc < 4; kc++) {
        int d0 = kc*8 + tg;
        aQ[kc][0] = __float_as_uint(Qb[(size_t)g*DK + d0]);
        aQ[kc][1] = __float_as_uint(Qb[(size_t)(g+8)*DK + d0]);
        aQ[kc][2] = __float_as_uint(Qb[(size_t)g*DK + d0 + 4]);
        aQ[kc][3] = __float_as_uint(Qb[(size_t)(g+8)*DK + d0 + 4]);
    }

    float o[4][4];
    #pragma unroll
    for (int i = 0; i < 4; i++)
        #pragma unroll
        for (int j = 0; j < 4; j++) o[i][j] = 0.f;
    float m0 = -1e30f, m1 = -1e30f, l0 = 0.f, l1 = 0.f;

    const float4* K4 = (const float4*)(g_K + bh*L_*DK);
    const float4* V4 = (const float4*)(g_V + bh*L_*DK);
    const float*  mrowg = mask + (size_t)b*L_;

    auto issue_tile = [&](int kt, int buf) {
        #pragma unroll
        for (int i = 0; i < 4; i++) {
            int f = t + 128*i;
            int row = f >> 3, col = (f & 7) * 4;
            unsigned kd = (unsigned)__cvta_generic_to_shared(&Ks[buf][row*36 + col]);
            unsigned vd = (unsigned)__cvta_generic_to_shared(&Vs[buf][row*40 + col]);
            CP_ASYNC16(kd, K4 + kt*512 + f);
            CP_ASYNC16(vd, V4 + kt*512 + f);
        }
        if (t < 16) {
            unsigned md = (unsigned)__cvta_generic_to_shared(&msk[buf][t*4]);
            CP_ASYNC16(md, mrowg + kt*64 + t*4);
        }
        CP_COMMIT();
    };

    issue_tile(0, 0);

    const int NT = L_/64;
    for (int kt = 0; kt < NT; kt++) {
        const int buf = kt & 1;
        CP_WAIT0();
        __syncthreads();   // tile kt visible to all; all warps done with buf (prev iter)
        if (kt + 1 < NT) issue_tile(kt + 1, buf ^ 1);

        const float* Kb = Ks[buf];
        const float* Vb = Vs[buf];
        const float* mk = msk[buf];

        // ---- S = Q.K^T : 8 n-chunks x 4 k-chunks of m16n8k8
        float sc[8][4];
        #pragma unroll
        for (int nf = 0; nf < 8; nf++) {
            float c0 = 0.f, c1 = 0.f, c2 = 0.f, c3 = 0.f;
            #pragma unroll
            for (int kc = 0; kc < 4; kc++) {
                const float* kr = Kb + (nf*8 + g)*36 + kc*8 + tg;
                unsigned b0 = __float_as_uint(kr[0]);
                unsigned b1 = __float_as_uint(kr[4]);
                mma_tf32(c0, c1, c2, c3, aQ[kc][0], aQ[kc][1], aQ[kc][2], aQ[kc][3], b0, b1);
            }
            sc[nf][0] = c0; sc[nf][1] = c1; sc[nf][2] = c2; sc[nf][3] = c3;
        }

        // ---- key mask (mask==1 keys -> -1e30)
        const int k2 = 2*tg;
        #pragma unroll
        for (int nf = 0; nf < 8; nf++) {
            float mk0 = mk[nf*8 + k2], mk1 = mk[nf*8 + k2 + 1];
            if (mk0 > 0.5f) { sc[nf][0] = -1e30f; sc[nf][2] = -1e30f; }
            if (mk1 > 0.5f) { sc[nf][1] = -1e30f; sc[nf][3] = -1e30f; }
        }

        // ---- online softmax (rows g and g+8)
        float tm0 = -1e30f, tm1 = -1e30f;
        #pragma unroll
        for (int nf = 0; nf < 8; nf++) {
            tm0 = fmaxf(tm0, fmaxf(sc[nf][0], sc[nf][1]));
            tm1 = fmaxf(tm1, fmaxf(sc[nf][2], sc[nf][3]));
        }
        tm0 = fmaxf(tm0, __shfl_xor_sync(0xffffffffu, tm0, 1));
        tm0 = fmaxf(tm0, __shfl_xor_sync(0xffffffffu, tm0, 2));
        tm1 = fmaxf(tm1, __shfl_xor_sync(0xffffffffu, tm1, 1));
        tm1 = fmaxf(tm1, __shfl_xor_sync(0xffffffffu, tm1, 2));

        float mn0 = fmaxf(m0, tm0), mn1 = fmaxf(m1, tm1);
        float rs0 = __expf(m0 - mn0), rs1 = __expf(m1 - mn1);
        m0 = mn0; m1 = mn1;

        float ps0 = 0.f, ps1 = 0.f;
        #pragma unroll
        for (int nf = 0; nf < 8; nf++) {
            sc[nf][0] = __expf(sc[nf][0] - mn0);
            sc[nf][1] = __expf(sc[nf][1] - mn0);
            sc[nf][2] = __expf(sc[nf][2] - mn1);
            sc[nf][3] = __expf(sc[nf][3] - mn1);
            ps0 += sc[nf][0] + sc[nf][1];
            ps1 += sc[nf][2] + sc[nf][3];
        }
        ps0 += __shfl_xor_sync(0xffffffffu, ps0, 1);
        ps0 += __shfl_xor_sync(0xffffffffu, ps0, 2);
        ps1 += __shfl_xor_sync(0xffffffffu, ps1, 1);
        ps1 += __shfl_xor_sync(0xffffffffu, ps1, 2);
        l0 = l0*rs0 + ps0;
        l1 = l1*rs1 + ps1;

        #pragma unroll
        for (int nf = 0; nf < 4; nf++) {
            o[nf][0] *= rs0; o[nf][1] *= rs0;
            o[nf][2] *= rs1; o[nf][3] *= rs1;
        }

        // ---- O += P.V
        const int srcA = (lane & ~3) | (tg >> 1);
        const int srcB = srcA + 2;
        const bool odd = (tg & 1);
        #pragma unroll
        for (int kc = 0; kc < 8; kc++) {
            float v0a = __shfl_sync(0xffffffffu, sc[kc][0], srcA);
            float v1a = __shfl_sync(0xffffffffu, sc[kc][1], srcA);
            float v2a = __shfl_sync(0xffffffffu, sc[kc][2], srcA);
            float v3a = __shfl_sync(0xffffffffu, sc[kc][3], srcA);
            float v0b = __shfl_sync(0xffffffffu, sc[kc][0], srcB);
            float v1b = __shfl_sync(0xffffffffu, sc[kc][1], srcB);
            float v2b = __shfl_sync(0xffffffffu, sc[kc][2], srcB);
            float v3b = __shfl_sync(0xffffffffu, sc[kc][3], srcB);
            unsigned aP0 = cvt_tf32(odd ? v1a : v0a);
            unsigned aP1 = cvt_tf32(odd ? v3a : v2a);
            unsigned aP2 = cvt_tf32(odd ? v1b : v0b);
            unsigned aP3 = cvt_tf32(odd ? v3b : v2b);
            #pragma unroll
            for (int nf = 0; nf < 4; nf++) {
                const float* vr = Vb + (kc*8 + tg)*40 + nf*8 + g;
                unsigned b0 = __float_as_uint(vr[0]);
                unsigned b1 = __float_as_uint(vr[4*40]);
                mma_tf32(o[nf][0], o[nf][1], o[nf][2], o[nf][3], aP0, aP1, aP2, aP3, b0, b1);
            }
        }
        // NOTE: no trailing barrier — buf is only overwritten after the next
        // iteration's top-of-loop __syncthreads, which orders all warps' reads.
    }

    // epilogue: O /= l, query-mask (mask==0 rows zeroed), write g_head
    float qm0 = mrowg[q0 + g], qm1 = mrowg[q0 + g + 8];
    float i0 = (qm0 > 0.5f) ? (1.f/l0) : 0.f;
    float i1 = (qm1 > 0.5f) ? (1.f/l1) : 0.f;
    float* h0 = g_head + ((size_t)b*L_ + q0 + g)*DM + h*DK;
    float* h1 = g_head + ((size_t)b*L_ + q0 + g + 8)*DM + h*DK;
    #pragma unroll
    for (int nf = 0; nf < 4; nf++) {
        int col = nf*8 + 2*tg;
        *(float2*)(h0 + col) = make_float2(o[nf][0]*i0, o[nf][1]*i0);
        *(float2*)(h1 + col) = make_float2(o[nf][2]*i1, o[nf][3]*i1);
    }
}

// ---------------------------------------------------------------------------
// Kernel 3: out = (head @ Wo)^T on tf32 mma.sync.
// grid (L/64, B), 128 thr = 4 warps; warp owns m16 head-rows x n128 out-cols.
// Wo staged transposed per 32-wide k-chunk: Wt[j=0..127][c'=0..31], stride 36
// -> B-frag bank index 4g+tg, conflict-free.
// ---------------------------------------------------------------------------
__global__ __launch_bounds__(128) void outproj_kernel(const float* __restrict__ Wo,
                                                      float* __restrict__ out) {
    __shared__ float Wt[128*36];
    const int t = threadIdx.x;
    const int lane = t & 31, w = t >> 5;
    const int g = lane >> 2, tg = lane & 3;
    const int l0 = blockIdx.x*64;
    const int b = blockIdx.y;

    float cq[16][4];
    #pragma unroll
    for (int i = 0; i < 16; i++)
        #pragma unroll
        for (int j = 0; j < 4; j++) cq[i][j] = 0.f;

    const float* hb = g_head + ((size_t)b*L_ + l0 + w*16)*DM;

    for (int ccb = 0; ccb < 4; ccb++) {            // k-chunks of 32
        __syncthreads();
        // stage Wo chunk transposed: Wt[j][c'] = Wo[(ccb*32+c')*128 + j]
        #pragma unroll
        for (int i = 0; i < 32; i++) {
            int idx = t + i*128;                   // coalesced read
            int cc = idx >> 7, j = idx & 127;
            Wt[j*36 + cc] = __uint_as_float(cvt_tf32(Wo[(ccb*32 + cc)*128 + j]));
        }
        __syncthreads();

        // A-frags from head (fp32 -> tf32): rows w*16+{g,g+8}, cols ccb*32+kc*8+tg(+4)
        unsigned aH[4][4];
        #pragma unroll
        for (int kc = 0; kc < 4; kc++) {
            int c0 = ccb*32 + kc*8 + tg;
            aH[kc][0] = cvt_tf32(hb[(size_t)g*DM + c0]);
            aH[kc][1] = cvt_tf32(hb[(size_t)(g+8)*DM + c0]);
            aH[kc][2] = cvt_tf32(hb[(size_t)g*DM + c0 + 4]);
            aH[kc][3] = cvt_tf32(hb[(size_t)(g+8)*DM + c0 + 4]);
        }

        #pragma unroll
        for (int nf = 0; nf < 16; nf++) {
            #pragma unroll
            for (int kc = 0; kc < 4; kc++) {
                const float* wr = Wt + (nf*8 + g)*36 + kc*8 + tg;
                unsigned b0 = __float_as_uint(wr[0]);
                unsigned b1 = __float_as_uint(wr[4]);
                mma_tf32(cq[nf][0], cq[nf][1], cq[nf][2], cq[nf][3],
                         aH[kc][0], aH[kc][1], aH[kc][2], aH[kc][3], b0, b1);
            }
        }
    }

    // transposed store: out[b][d][l], d = nf*8+2tg(+1), l = l0+w*16+g(+8)
    float* ob = out + (size_t)b*DM*L_;
    const int lA = l0 + w*16 + g, lB = lA + 8;
    #pragma unroll
    for (int nf = 0; nf < 16; nf++) {
        int d0 = nf*8 + 2*tg;
        ob[(size_t)d0*L_ + lA]       = cq[nf][0];
        ob[(size_t)(d0+1)*L_ + lA]   = cq[nf][1];
        ob[(size_t)d0*L_ + lB]       = cq[nf][2];
        ob[(size_t)(d0+1)*L_ + lB]   = cq[nf][3];
    }
}

extern "C" void kernel_launch(void* const* d_in, const int* in_sizes, int n_in,
                              void* d_out, int out_size) {
    const float* x    = (const float*)d_in[0];
    const float* mask = (const float*)d_in[1];
    const float* Wq   = (const float*)d_in[2];
    const float* Wk   = (const float*)d_in[3];
    const float* Wv   = (const float*)d_in[4];
    const float* Wo   = (const float*)d_in[5];
    float* out = (float*)d_out;

    qkv_kernel<<<dim3(L_/64, B_, 12), 128>>>(x, Wq, Wk, Wv);
    attn_kernel<<<dim3(L_/64, NH, B_), 128>>>(mask);
    outproj_kernel<<<dim3(L_/64, B_), 128>>>(Wo, out);
}

// round 17
// speedup vs baseline: 3.8456x; 1.0279x over previous
#include <cuda_runtime.h>
#include <cstdint>

#define B_  8
#define L_  2048
#define DM  128
#define NH  4
#define DK  32

typedef unsigned long long ull;

// Scratch (allocation-free rule: __device__ globals)
__device__ float g_Q[B_*NH*L_*DK];   // tf32-rounded
__device__ float g_K[B_*NH*L_*DK];   // tf32-rounded
__device__ float g_V[B_*NH*L_*DK];   // tf32-rounded
__device__ float g_head[B_*L_*DM];

__device__ __forceinline__ unsigned cvt_tf32(float f) {
    unsigned u; asm("cvt.rna.tf32.f32 %0, %1;" : "=r"(u) : "f"(f)); return u;
}

// cp.async 16B: gmem -> smem, register-free
#define CP_ASYNC16(dst_u32, src_ptr) \
    asm volatile("cp.async.ca.shared.global [%0], [%1], 16;" :: "r"(dst_u32), "l"(src_ptr))
#define CP_COMMIT()  asm volatile("cp.async.commit_group;")
#define CP_WAIT0()   asm volatile("cp.async.wait_group 0;")

// D += A(m16k8,tf32) * B(k8n8,tf32), fp32 accumulate
__device__ __forceinline__ void mma_tf32(float& c0, float& c1, float& c2, float& c3,
                                         unsigned a0, unsigned a1, unsigned a2, unsigned a3,
                                         unsigned b0, unsigned b1) {
    asm("mma.sync.aligned.m16n8k8.row.col.f32.tf32.tf32.f32 "
        "{%0,%1,%2,%3}, {%4,%5,%6,%7}, {%8,%9}, {%0,%1,%2,%3};"
        : "+f"(c0), "+f"(c1), "+f"(c2), "+f"(c3)
        : "r"(a0), "r"(a1), "r"(a2), "r"(a3), "r"(b0), "r"(b1));
}

// ---------------------------------------------------------------------------
// Kernel 1: QKV projection on tf32 mma.sync, all 4 heads per block.
// grid (L/64, B, 3): z = matrix. 128 thr = 4 warps, warp owns m16 l-rows x
// n128 (4 heads x 32). W double-buffer-staged per 32-wide k-chunk; x A-frags
// loaded once per matrix (was once per head: 4x LDG traffic reduction).
// ---------------------------------------------------------------------------
__global__ __launch_bounds__(128) void qkv_kernel(const float* __restrict__ x,
                                                  const float* __restrict__ Wq,
                                                  const float* __restrict__ Wk,
                                                  const float* __restrict__ Wv) {
    __shared__ float Wt[2][128*36];
    const int t = threadIdx.x;
    const int lane = t & 31, w = t >> 5;
    const int g = lane >> 2, tg = lane & 3;
    const int l0 = blockIdx.x*64;
    const int b = blockIdx.y;
    const int matsel = blockIdx.z;

    const float* Wsel = (matsel==0 ? Wq : (matsel==1 ? Wk : Wv));

    // stage W k-chunk 0 transposed: Wt[jg][cc] = W[h= jg>>5][d= cc][j= jg&31]
    #pragma unroll
    for (int i = 0; i < 32; i++) {
        int idx = t + i*128;
        int cc = idx >> 7, jg = idx & 127;            // coalesced read in j
        Wt[0][jg*36 + cc] =
            __uint_as_float(cvt_tf32(Wsel[((jg >> 5)*DM + cc)*DK + (jg & 31)]));
    }
    __syncthreads();

    float cq[16][4];
    #pragma unroll
    for (int i = 0; i < 16; i++)
        #pragma unroll
        for (int j = 0; j < 4; j++) cq[i][j] = 0.f;

    const float* xb = x + (size_t)b*DM*L_ + l0 + w*16;

    for (int ccb = 0; ccb < 4; ccb++) {               // k-chunks of 32
        // A-frags for this chunk (issue LDGs first to hide latency)
        unsigned aH[4][4];
        #pragma unroll
        for (int kc = 0; kc < 4; kc++) {
            int d0 = ccb*32 + kc*8 + tg;
            aH[kc][0] = cvt_tf32(__ldg(xb + (size_t)d0*L_ + g));
            aH[kc][1] = cvt_tf32(__ldg(xb + (size_t)d0*L_ + g + 8));
            aH[kc][2] = cvt_tf32(__ldg(xb + (size_t)(d0+4)*L_ + g));
            aH[kc][3] = cvt_tf32(__ldg(xb + (size_t)(d0+4)*L_ + g + 8));
        }

        // stage next W chunk into the other buffer (overlaps with MMAs)
        if (ccb < 3) {
            #pragma unroll
            for (int i = 0; i < 32; i++) {
                int idx = t + i*128;
                int cc = idx >> 7, jg = idx & 127;
                Wt[(ccb+1)&1][jg*36 + cc] =
                    __uint_as_float(cvt_tf32(Wsel[((jg >> 5)*DM + (ccb+1)*32 + cc)*DK + (jg & 31)]));
            }
        }

        const float* Wb = Wt[ccb & 1];
        #pragma unroll
        for (int nf = 0; nf < 16; nf++) {
            #pragma unroll
            for (int kc = 0; kc < 4; kc++) {
                const float* wr = Wb + (nf*8 + g)*36 + kc*8 + tg;
                unsigned b0 = __float_as_uint(wr[0]);
                unsigned b1 = __float_as_uint(wr[4]);
                mma_tf32(cq[nf][0], cq[nf][1], cq[nf][2], cq[nf][3],
                         aH[kc][0], aH[kc][1], aH[kc][2], aH[kc][3], b0, b1);
            }
        }
        __syncthreads();      // next buffer fully staged; current buffer free
    }

    // epilogue: scale (Q only), tf32-round, store per head
    const float sc = (matsel == 0) ? 0.17677669529663687f : 1.0f;  // 1/sqrt(32) into Q
    float* base = (matsel==0 ? g_Q : (matsel==1 ? g_K : g_V));
    #pragma unroll
    for (int nf = 0; nf < 16; nf++) {
        int h = nf >> 2;
        int j = (nf & 3)*8 + 2*tg;
        float* dst = base + (((size_t)b*NH + h)*L_ + l0 + w*16)*DK + j;
        float2 v0 = make_float2(__uint_as_float(cvt_tf32(cq[nf][0]*sc)),
                                __uint_as_float(cvt_tf32(cq[nf][1]*sc)));
        float2 v1 = make_float2(__uint_as_float(cvt_tf32(cq[nf][2]*sc)),
                                __uint_as_float(cvt_tf32(cq[nf][3]*sc)));
        *(float2*)(dst + (size_t)g*DK)       = v0;
        *(float2*)(dst + (size_t)(g+8)*DK)   = v1;
    }
}

// ---------------------------------------------------------------------------
// Kernel 2: flash attention, tf32 mma.sync, 64-key tiles, cp.async double
// buffer, single barrier per tile. grid (L/64, NH, B), 128 threads = 4 warps.
// ---------------------------------------------------------------------------
__global__ __launch_bounds__(128) void attn_kernel(const float* __restrict__ mask) {
    __shared__ __align__(16) float Ks[2][64*36];
    __shared__ __align__(16) float Vs[2][64*40];
    __shared__ __align__(16) float msk[2][64];

    const int t = threadIdx.x;
    const int lane = t & 31, w = t >> 5;
    const int g = lane >> 2, tg = lane & 3;
    const int h = blockIdx.y, b = blockIdx.z;
    const size_t bh = (size_t)b*NH + h;
    const int q0 = blockIdx.x*64 + w*16;

    // Q fragments (tf32-rounded in memory)
    unsigned aQ[4][4];
    const float* Qb = g_Q + (bh*L_ + q0)*DK;
    #pragma unroll
    for (int kc = 0; kc < 4; kc++) {
        int d0 = kc*8 + tg;
        aQ[kc][0] = __float_as_uint(Qb[(size_t)g*DK + d0]);
        aQ[kc][1] = __float_as_uint(Qb[(size_t)(g+8)*DK + d0]);
        aQ[kc][2] = __float_as_uint(Qb[(size_t)g*DK + d0 + 4]);
        aQ[kc][3] = __float_as_uint(Qb[(size_t)(g+8)*DK + d0 + 4]);
    }

    float o[4][4];
    #pragma unroll
    for (int i = 0; i < 4; i++)
        #pragma unroll
        for (int j = 0; j < 4; j++) o[i][j] = 0.f;
    float m0 = -1e30f, m1 = -1e30f, l0 = 0.f, l1 = 0.f;

    const float4* K4 = (const float4*)(g_K + bh*L_*DK);
    const float4* V4 = (const float4*)(g_V + bh*L_*DK);
    const float*  mrowg = mask + (size_t)b*L_;

    auto issue_tile = [&](int kt, int buf) {
        #pragma unroll
        for (int i = 0; i < 4; i++) {
            int f = t + 128*i;
            int row = f >> 3, col = (f & 7) * 4;
            unsigned kd = (unsigned)__cvta_generic_to_shared(&Ks[buf][row*36 + col]);
            unsigned vd = (unsigned)__cvta_generic_to_shared(&Vs[buf][row*40 + col]);
            CP_ASYNC16(kd, K4 + kt*512 + f);
            CP_ASYNC16(vd, V4 + kt*512 + f);
        }
        if (t < 16) {
            unsigned md = (unsigned)__cvta_generic_to_shared(&msk[buf][t*4]);
            CP_ASYNC16(md, mrowg + kt*64 + t*4);
        }
        CP_COMMIT();
    };

    issue_tile(0, 0);

    const int NT = L_/64;
    for (int kt = 0; kt < NT; kt++) {
        const int buf = kt & 1;
        CP_WAIT0();
        __syncthreads();   // tile kt visible to all; all warps done with buf (prev iter)
        if (kt + 1 < NT) issue_tile(kt + 1, buf ^ 1);

        const float* Kb = Ks[buf];
        const float* Vb = Vs[buf];
        const float* mk = msk[buf];

        // ---- S = Q.K^T : 8 n-chunks x 4 k-chunks of m16n8k8
        float sc[8][4];
        #pragma unroll
        for (int nf = 0; nf < 8; nf++) {
            float c0 = 0.f, c1 = 0.f, c2 = 0.f, c3 = 0.f;
            #pragma unroll
            for (int kc = 0; kc < 4; kc++) {
                const float* kr = Kb + (nf*8 + g)*36 + kc*8 + tg;
                unsigned b0 = __float_as_uint(kr[0]);
                unsigned b1 = __float_as_uint(kr[4]);
                mma_tf32(c0, c1, c2, c3, aQ[kc][0], aQ[kc][1], aQ[kc][2], aQ[kc][3], b0, b1);
            }
            sc[nf][0] = c0; sc[nf][1] = c1; sc[nf][2] = c2; sc[nf][3] = c3;
        }

        // ---- key mask (mask==1 keys -> -1e30)
        const int k2 = 2*tg;
        #pragma unroll
        for (int nf = 0; nf < 8; nf++) {
            float mk0 = mk[nf*8 + k2], mk1 = mk[nf*8 + k2 + 1];
            if (mk0 > 0.5f) { sc[nf][0] = -1e30f; sc[nf][2] = -1e30f; }
            if (mk1 > 0.5f) { sc[nf][1] = -1e30f; sc[nf][3] = -1e30f; }
        }

        // ---- online softmax (rows g and g+8)
        float tm0 = -1e30f, tm1 = -1e30f;
        #pragma unroll
        for (int nf = 0; nf < 8; nf++) {
            tm0 = fmaxf(tm0, fmaxf(sc[nf][0], sc[nf][1]));
            tm1 = fmaxf(tm1, fmaxf(sc[nf][2], sc[nf][3]));
        }
        tm0 = fmaxf(tm0, __shfl_xor_sync(0xffffffffu, tm0, 1));
        tm0 = fmaxf(tm0, __shfl_xor_sync(0xffffffffu, tm0, 2));
        tm1 = fmaxf(tm1, __shfl_xor_sync(0xffffffffu, tm1, 1));
        tm1 = fmaxf(tm1, __shfl_xor_sync(0xffffffffu, tm1, 2));

        float mn0 = fmaxf(m0, tm0), mn1 = fmaxf(m1, tm1);
        float rs0 = __expf(m0 - mn0), rs1 = __expf(m1 - mn1);
        m0 = mn0; m1 = mn1;

        float ps0 = 0.f, ps1 = 0.f;
        #pragma unroll
        for (int nf = 0; nf < 8; nf++) {
            sc[nf][0] = __expf(sc[nf][0] - mn0);
            sc[nf][1] = __expf(sc[nf][1] - mn0);
            sc[nf][2] = __expf(sc[nf][2] - mn1);
            sc[nf][3] = __expf(sc[nf][3] - mn1);
            ps0 += sc[nf][0] + sc[nf][1];
            ps1 += sc[nf][2] + sc[nf][3];
        }
        ps0 += __shfl_xor_sync(0xffffffffu, ps0, 1);
        ps0 += __shfl_xor_sync(0xffffffffu, ps0, 2);
        ps1 += __shfl_xor_sync(0xffffffffu, ps1, 1);
        ps1 += __shfl_xor_sync(0xffffffffu, ps1, 2);
        l0 = l0*rs0 + ps0;
        l1 = l1*rs1 + ps1;

        #pragma unroll
        for (int nf = 0; nf < 4; nf++) {
            o[nf][0] *= rs0; o[nf][1] *= rs0;
            o[nf][2] *= rs1; o[nf][3] *= rs1;
        }

        // ---- O += P.V
        const int srcA = (lane & ~3) | (tg >> 1);
        const int srcB = srcA + 2;
        const bool odd = (tg & 1);
        #pragma unroll
        for (int kc = 0; kc < 8; kc++) {
            float v0a = __shfl_sync(0xffffffffu, sc[kc][0], srcA);
            float v1a = __shfl_sync(0xffffffffu, sc[kc][1], srcA);
            float v2a = __shfl_sync(0xffffffffu, sc[kc][2], srcA);
            float v3a = __shfl_sync(0xffffffffu, sc[kc][3], srcA);
            float v0b = __shfl_sync(0xffffffffu, sc[kc][0], srcB);
            float v1b = __shfl_sync(0xffffffffu, sc[kc][1], srcB);
            float v2b = __shfl_sync(0xffffffffu, sc[kc][2], srcB);
            float v3b = __shfl_sync(0xffffffffu, sc[kc][3], srcB);
            unsigned aP0 = cvt_tf32(odd ? v1a : v0a);
            unsigned aP1 = cvt_tf32(odd ? v3a : v2a);
            unsigned aP2 = cvt_tf32(odd ? v1b : v0b);
            unsigned aP3 = cvt_tf32(odd ? v3b : v2b);
            #pragma unroll
            for (int nf = 0; nf < 4; nf++) {
                const float* vr = Vb + (kc*8 + tg)*40 + nf*8 + g;
                unsigned b0 = __float_as_uint(vr[0]);
                unsigned b1 = __float_as_uint(vr[4*40]);
                mma_tf32(o[nf][0], o[nf][1], o[nf][2], o[nf][3], aP0, aP1, aP2, aP3, b0, b1);
            }
        }
        // no trailing barrier — next iteration's top-of-loop barrier orders reuse
    }

    // epilogue: O /= l, query-mask (mask==0 rows zeroed), write g_head
    float qm0 = mrowg[q0 + g], qm1 = mrowg[q0 + g + 8];
    float i0 = (qm0 > 0.5f) ? (1.f/l0) : 0.f;
    float i1 = (qm1 > 0.5f) ? (1.f/l1) : 0.f;
    float* h0 = g_head + ((size_t)b*L_ + q0 + g)*DM + h*DK;
    float* h1 = g_head + ((size_t)b*L_ + q0 + g + 8)*DM + h*DK;
    #pragma unroll
    for (int nf = 0; nf < 4; nf++) {
        int col = nf*8 + 2*tg;
        *(float2*)(h0 + col) = make_float2(o[nf][0]*i0, o[nf][1]*i0);
        *(float2*)(h1 + col) = make_float2(o[nf][2]*i1, o[nf][3]*i1);
    }
}

// ---------------------------------------------------------------------------
// Kernel 3: out = (head @ Wo)^T on tf32 mma.sync, n-split for occupancy.
// grid (L/64, 2, B): y picks 64 of the 128 output columns. 128 thr = 4 warps;
// warp owns m16 head-rows x n64 out-cols. 512 CTAs (~3.5/SM) vs 256 before.
// ---------------------------------------------------------------------------
__global__ __launch_bounds__(128) void outproj_kernel(const float* __restrict__ Wo,
                                                      float* __restrict__ out) {
    __shared__ float Wt[64*36];
    const int t = threadIdx.x;
    const int lane = t & 31, w = t >> 5;
    const int g = lane >> 2, tg = lane & 3;
    const int l0 = blockIdx.x*64;
    const int n0 = blockIdx.y*64;
    const int b = blockIdx.z;

    float cq[8][4];
    #pragma unroll
    for (int i = 0; i < 8; i++)
        #pragma unroll
        for (int j = 0; j < 4; j++) cq[i][j] = 0.f;

    const float* hb = g_head + ((size_t)b*L_ + l0 + w*16)*DM;

    for (int ccb = 0; ccb < 4; ccb++) {            // k-chunks of 32
        __syncthreads();
        // stage Wo chunk transposed: Wt[j][cc] = Wo[(ccb*32+cc)*128 + n0 + j]
        #pragma unroll
        for (int i = 0; i < 16; i++) {
            int idx = t + i*128;
            int cc = idx >> 6, j = idx & 63;       // coalesced 64-float runs
            Wt[j*36 + cc] = __uint_as_float(cvt_tf32(Wo[(ccb*32 + cc)*128 + n0 + j]));
        }
        __syncthreads();

        unsigned aH[4][4];
        #pragma unroll
        for (int kc = 0; kc < 4; kc++) {
            int c0 = ccb*32 + kc*8 + tg;
            aH[kc][0] = cvt_tf32(hb[(size_t)g*DM + c0]);
            aH[kc][1] = cvt_tf32(hb[(size_t)(g+8)*DM + c0]);
            aH[kc][2] = cvt_tf32(hb[(size_t)g*DM + c0 + 4]);
            aH[kc][3] = cvt_tf32(hb[(size_t)(g+8)*DM + c0 + 4]);
        }

        #pragma unroll
        for (int nf = 0; nf < 8; nf++) {
            #pragma unroll
            for (int kc = 0; kc < 4; kc++) {
                const float* wr = Wt + (nf*8 + g)*36 + kc*8 + tg;
                unsigned b0 = __float_as_uint(wr[0]);
                unsigned b1 = __float_as_uint(wr[4]);
                mma_tf32(cq[nf][0], cq[nf][1], cq[nf][2], cq[nf][3],
                         aH[kc][0], aH[kc][1], aH[kc][2], aH[kc][3], b0, b1);
            }
        }
    }

    // transposed store: out[b][d][l]
    float* ob = out + (size_t)b*DM*L_;
    const int lA = l0 + w*16 + g, lB = lA + 8;
    #pragma unroll
    for (int nf = 0; nf < 8; nf++) {
        int d0 = n0 + nf*8 + 2*tg;
        ob[(size_t)d0*L_ + lA]       = cq[nf][0];
        ob[(size_t)(d0+1)*L_ + lA]   = cq[nf][1];
        ob[(size_t)d0*L_ + lB]       = cq[nf][2];
        ob[(size_t)(d0+1)*L_ + lB]   = cq[nf][3];
    }
}

extern "C" void kernel_launch(void* const* d_in, const int* in_sizes, int n_in,
                              void* d_out, int out_size) {
    const float* x    = (const float*)d_in[0];
    const float* mask = (const float*)d_in[1];
    const float* Wq   = (const float*)d_in[2];
    const float* Wk   = (const float*)d_in[3];
    const float* Wv   = (const float*)d_in[4];
    const float* Wo   = (const float*)d_in[5];
    float* out = (float*)d_out;

    qkv_kernel<<<dim3(L_/64, B_, 3), 128>>>(x, Wq, Wk, Wv);
    attn_kernel<<<dim3(L_/64, NH, B_), 128>>>(mask);
    outproj_kernel<<<dim3(L_/64, 2, B_), 128>>>(Wo, out);
}